// round 10
// baseline (speedup 1.0000x reference)
#include <cuda_runtime.h>
#include <cstdint>

// ---------------- problem constants ----------------
#define Bb 2
#define Ss 2048
#define Hh 1536
#define NHq 12
#define NKVh 4
#define Dd 128
#define Tt (Bb*Ss)          // 4096
#define Ee 8
#define IEXP 512
#define ISH 1024
#define SCALEf 0.0078125f
#define RESMf 0.22f
#define EPSf 1e-6f

// ---------------- scratch (device globals; addresses resolved via cudaGetSymbolAddress) ----------------
__device__ float g_xnorm [Tt*Hh];
__device__ float g_q     [Tt*Hh];
__device__ float g_k     [Tt*NKVh*Dd];
__device__ float g_v     [Tt*NKVh*Dd];
__device__ float g_attn  [Tt*Hh];
__device__ float g_hidden[Tt*Hh];
__device__ float g_x2    [Tt*Hh];
__device__ float g_shgate[Tt*2*ISH];
__device__ float g_shh   [Tt*ISH];
__device__ float g_shared[Tt*Hh];
__device__ float g_gbuf  [Ee*Tt*IEXP];
__device__ float g_ubuf  [Ee*Tt*IEXP];
__device__ float g_ydown [Tt*2*Hh];
// device-symbol-only bookkeeping (written AND read exclusively inside kernels)
__device__ int   g_elist [Ee*Tt];
__device__ int   g_ecount[Ee];
__device__ float g_rwflat[Tt*2];

// ---------------- rmsnorm ----------------
__global__ __launch_bounds__(256) void rmsnorm_kernel(
    const float* __restrict__ x, const float* __restrict__ w, float* __restrict__ y)
{
    int t = blockIdx.x;
    const float* xr = x + (size_t)t*Hh;
    float s = 0.f;
    for (int i = threadIdx.x; i < Hh; i += 256) { float v = xr[i]; s += v*v; }
    #pragma unroll
    for (int o = 16; o > 0; o >>= 1) s += __shfl_xor_sync(0xffffffffu, s, o);
    __shared__ float red[8];
    if ((threadIdx.x & 31) == 0) red[threadIdx.x >> 5] = s;
    __syncthreads();
    float tot = 0.f;
    #pragma unroll
    for (int wv = 0; wv < 8; wv++) tot += red[wv];
    float inv = rsqrtf(tot * (1.0f/(float)Hh) + EPSf);
    float* yr = y + (size_t)t*Hh;
    for (int i = threadIdx.x; i < Hh; i += 256) yr[i] = w[i]*xr[i]*inv;
}

// ---------------- register-tiled TN GEMM: C[M,N] = alpha*A[M,K]@B[N,K]^T (+res) ----------------
__global__ __launch_bounds__(256) void gemm_tn(
    const float* __restrict__ A, int lda,
    const float* __restrict__ B, int ldb,
    float* __restrict__ C, int ldc,
    int M, int N, int K, float alpha,
    const float* __restrict__ res)
{
    __shared__ float As[16][128];
    __shared__ float Bs[16][128];
    const int tid = threadIdx.x;
    const int m0 = blockIdx.y * 128;
    const int n0 = blockIdx.x * 128;
    const int tx = tid & 15;
    const int ty = tid >> 4;
    float acc[8][8];
    #pragma unroll
    for (int i = 0; i < 8; i++)
        #pragma unroll
        for (int j = 0; j < 8; j++) acc[i][j] = 0.f;

    for (int k0 = 0; k0 < K; k0 += 16) {
        #pragma unroll
        for (int i = 0; i < 2; i++) {
            int v = tid + i*256;
            int row = v >> 2;
            int kq = (v & 3) << 2;
            int gm = m0 + row;
            float4 av = make_float4(0.f,0.f,0.f,0.f);
            if (gm < M) av = *(const float4*)(A + (size_t)gm*lda + k0 + kq);
            As[kq+0][row] = av.x; As[kq+1][row] = av.y;
            As[kq+2][row] = av.z; As[kq+3][row] = av.w;
            int gn = n0 + row;
            float4 bv = make_float4(0.f,0.f,0.f,0.f);
            if (gn < N) bv = *(const float4*)(B + (size_t)gn*ldb + k0 + kq);
            Bs[kq+0][row] = bv.x; Bs[kq+1][row] = bv.y;
            Bs[kq+2][row] = bv.z; Bs[kq+3][row] = bv.w;
        }
        __syncthreads();
        #pragma unroll
        for (int kk = 0; kk < 16; kk++) {
            float a[8], b[8];
            *(float4*)&a[0] = *(const float4*)&As[kk][ty*8];
            *(float4*)&a[4] = *(const float4*)&As[kk][ty*8+4];
            *(float4*)&b[0] = *(const float4*)&Bs[kk][tx*8];
            *(float4*)&b[4] = *(const float4*)&Bs[kk][tx*8+4];
            #pragma unroll
            for (int i = 0; i < 8; i++)
                #pragma unroll
                for (int j = 0; j < 8; j++) acc[i][j] += a[i]*b[j];
        }
        __syncthreads();
    }
    #pragma unroll
    for (int i = 0; i < 8; i++) {
        int gm = m0 + ty*8 + i;
        if (gm >= M) continue;
        #pragma unroll
        for (int j = 0; j < 8; j += 4) {
            int gn = n0 + tx*8 + j;
            if (gn >= N) continue;
            float4 o;
            o.x = alpha*acc[i][j+0]; o.y = alpha*acc[i][j+1];
            o.z = alpha*acc[i][j+2]; o.w = alpha*acc[i][j+3];
            if (res) {
                float4 r = *(const float4*)(res + (size_t)gm*ldc + gn);
                o.x += r.x; o.y += r.y; o.z += r.z; o.w += r.w;
            }
            *(float4*)(C + (size_t)gm*ldc + gn) = o;
        }
    }
}

// ---------------- MoE per-expert GEMM (gathered A rows / scattered C rows) ----------------
__global__ __launch_bounds__(256) void moe_gemm(
    const float* __restrict__ Asrc, int lda,
    const float* __restrict__ W, int N, int K,
    float* __restrict__ C, int ldc,
    int gatherIn, int scatterOut)
{
    int e = blockIdx.z;
    int count = g_ecount[e];
    int m0 = blockIdx.y * 128;
    if (m0 >= count) return;
    const int* lst = g_elist + e*Tt;
    const float* B = W + (size_t)e * N * K;

    __shared__ float As[16][128];
    __shared__ float Bs[16][128];
    __shared__ int rowmap[128];
    const int tid = threadIdx.x;
    const int n0 = blockIdx.x * 128;
    const int tx = tid & 15;
    const int ty = tid >> 4;
    if (tid < 128) {
        int r = m0 + tid;
        int src = -1;
        if (r < count) src = gatherIn ? (lst[r] >> 1) : (e*Tt + r);
        rowmap[tid] = src;
    }
    __syncthreads();

    float acc[8][8];
    #pragma unroll
    for (int i = 0; i < 8; i++)
        #pragma unroll
        for (int j = 0; j < 8; j++) acc[i][j] = 0.f;

    for (int k0 = 0; k0 < K; k0 += 16) {
        #pragma unroll
        for (int i = 0; i < 2; i++) {
            int v = tid + i*256;
            int row = v >> 2;
            int kq = (v & 3) << 2;
            int src = rowmap[row];
            float4 av = make_float4(0.f,0.f,0.f,0.f);
            if (src >= 0) av = *(const float4*)(Asrc + (size_t)src*lda + k0 + kq);
            As[kq+0][row] = av.x; As[kq+1][row] = av.y;
            As[kq+2][row] = av.z; As[kq+3][row] = av.w;
            int gn = n0 + row;
            float4 bv = make_float4(0.f,0.f,0.f,0.f);
            if (gn < N) bv = *(const float4*)(B + (size_t)gn*K + k0 + kq);
            Bs[kq+0][row] = bv.x; Bs[kq+1][row] = bv.y;
            Bs[kq+2][row] = bv.z; Bs[kq+3][row] = bv.w;
        }
        __syncthreads();
        #pragma unroll
        for (int kk = 0; kk < 16; kk++) {
            float a[8], b[8];
            *(float4*)&a[0] = *(const float4*)&As[kk][ty*8];
            *(float4*)&a[4] = *(const float4*)&As[kk][ty*8+4];
            *(float4*)&b[0] = *(const float4*)&Bs[kk][tx*8];
            *(float4*)&b[4] = *(const float4*)&Bs[kk][tx*8+4];
            #pragma unroll
            for (int i = 0; i < 8; i++)
                #pragma unroll
                for (int j = 0; j < 8; j++) acc[i][j] += a[i]*b[j];
        }
        __syncthreads();
    }
    #pragma unroll
    for (int i = 0; i < 8; i++) {
        int r = m0 + ty*8 + i;
        if (r >= count) continue;
        int orow = scatterOut ? lst[r] : (e*Tt + r);
        #pragma unroll
        for (int j = 0; j < 8; j += 4) {
            int gn = n0 + tx*8 + j;
            if (gn >= N) continue;
            float4 o;
            o.x = acc[i][j+0]; o.y = acc[i][j+1];
            o.z = acc[i][j+2]; o.w = acc[i][j+3];
            *(float4*)(C + (size_t)orow*ldc + gn) = o;
        }
    }
}

// ---------------- RoPE ----------------
__global__ void rope_kernel(float* __restrict__ a, int nheads,
                            const int* __restrict__ pos_ids,
                            const float* __restrict__ cosb,
                            const float* __restrict__ sinb)
{
    int idx = blockIdx.x*256 + threadIdx.x;
    int total = Tt * nheads * 64;
    if (idx >= total) return;
    int dd = idx & 63;
    int hh = (idx >> 6) % nheads;
    int t  = idx / (64*nheads);
    int pos = pos_ids[t] & 4095;
    float c1 = cosb[pos*Dd + dd],      s1 = sinb[pos*Dd + dd];
    float c2 = cosb[pos*Dd + dd + 64], s2 = sinb[pos*Dd + dd + 64];
    float* base = a + (size_t)t*(nheads*Dd) + hh*Dd;
    float x1 = base[dd], x2 = base[dd+64];
    base[dd]     = x1*c1 - x2*s1;
    base[dd+64]  = x2*c2 + x1*s2;
}

// ---------------- flash attention, 32x32 tiles, static smem ----------------
__global__ __launch_bounds__(256) void attn_kernel(
    const float* __restrict__ Q, const float* __restrict__ Kg,
    const float* __restrict__ Vg, float* __restrict__ O)
{
    __shared__ float Qt[128][33];
    __shared__ float KV[128*33];
    __shared__ float Pt[32][33];
    int qt = blockIdx.x, h = blockIdx.y, b = blockIdx.z;
    int kvh = h / (NHq/NKVh);
    int tid = threadIdx.x;
    int tx = tid & 15, ty = tid >> 4;
    int tq0 = b*Ss + qt*32;

    #pragma unroll
    for (int i = 0; i < 4; i++) {
        int v = tid + i*256;
        int r = v >> 5;
        int dq = (v & 31) << 2;
        float4 qv = *(const float4*)(Q + (size_t)(tq0+r)*Hh + h*Dd + dq);
        Qt[dq+0][r] = qv.x * SCALEf;
        Qt[dq+1][r] = qv.y * SCALEf;
        Qt[dq+2][r] = qv.z * SCALEf;
        Qt[dq+3][r] = qv.w * SCALEf;
    }

    float m_i[2], l_i[2], acc[2][8];
    #pragma unroll
    for (int i = 0; i < 2; i++) {
        m_i[i] = -1e30f; l_i[i] = 0.f;
        #pragma unroll
        for (int j = 0; j < 8; j++) acc[i][j] = 0.f;
    }

    for (int kt = 0; kt <= qt; kt++) {
        int tk0 = b*Ss + kt*32;
        __syncthreads();
        #pragma unroll
        for (int i = 0; i < 4; i++) {
            int v = tid + i*256;
            int r = v >> 5;
            int dq = (v & 31) << 2;
            float4 kv = *(const float4*)(Kg + (size_t)(tk0+r)*(NKVh*Dd) + kvh*Dd + dq);
            KV[(dq+0)*33 + r] = kv.x; KV[(dq+1)*33 + r] = kv.y;
            KV[(dq+2)*33 + r] = kv.z; KV[(dq+3)*33 + r] = kv.w;
        }
        __syncthreads();

        float s[2][2];
        s[0][0]=s[0][1]=s[1][0]=s[1][1]=0.f;
        for (int d = 0; d < 128; d++) {
            float a0 = Qt[d][ty*2+0], a1 = Qt[d][ty*2+1];
            float b0 = KV[d*33 + tx*2+0], b1 = KV[d*33 + tx*2+1];
            s[0][0] += a0*b0; s[0][1] += a0*b1;
            s[1][0] += a1*b0; s[1][1] += a1*b1;
        }
        if (kt == qt) {
            #pragma unroll
            for (int i = 0; i < 2; i++)
                #pragma unroll
                for (int j = 0; j < 2; j++)
                    if (tx*2 + j > ty*2 + i) s[i][j] = -1e30f;
        }
        #pragma unroll
        for (int i = 0; i < 2; i++) {
            float mx = fmaxf(s[i][0], s[i][1]);
            #pragma unroll
            for (int o = 1; o < 16; o <<= 1) mx = fmaxf(mx, __shfl_xor_sync(0xffffffffu, mx, o));
            float mn = fmaxf(m_i[i], mx);
            float p0 = expf(s[i][0] - mn);
            float p1 = expf(s[i][1] - mn);
            float psum = p0 + p1;
            #pragma unroll
            for (int o = 1; o < 16; o <<= 1) psum += __shfl_xor_sync(0xffffffffu, psum, o);
            float f = expf(m_i[i] - mn);
            l_i[i] = l_i[i]*f + psum;
            m_i[i] = mn;
            #pragma unroll
            for (int j = 0; j < 8; j++) acc[i][j] *= f;
            Pt[tx*2+0][ty*2+i] = p0;
            Pt[tx*2+1][ty*2+i] = p1;
        }
        __syncthreads();
        #pragma unroll
        for (int i = 0; i < 4; i++) {
            int v = tid + i*256;
            int r = v >> 5;
            int dq = (v & 31) << 2;
            float4 vv = *(const float4*)(Vg + (size_t)(tk0+r)*(NKVh*Dd) + kvh*Dd + dq);
            *(float4*)(KV + r*128 + dq) = vv;
        }
        __syncthreads();
        for (int k = 0; k < 32; k++) {
            float a0 = Pt[k][ty*2+0], a1 = Pt[k][ty*2+1];
            float bb[8];
            *(float4*)&bb[0] = *(const float4*)(KV + k*128 + tx*8);
            *(float4*)&bb[4] = *(const float4*)(KV + k*128 + tx*8 + 4);
            #pragma unroll
            for (int j = 0; j < 8; j++) {
                acc[0][j] += a0*bb[j];
                acc[1][j] += a1*bb[j];
            }
        }
    }
    #pragma unroll
    for (int i = 0; i < 2; i++) {
        float inv = 1.0f / l_i[i];
        int t = tq0 + ty*2 + i;
        float4 o1, o2;
        o1.x = acc[i][0]*inv; o1.y = acc[i][1]*inv; o1.z = acc[i][2]*inv; o1.w = acc[i][3]*inv;
        o2.x = acc[i][4]*inv; o2.y = acc[i][5]*inv; o2.z = acc[i][6]*inv; o2.w = acc[i][7]*inv;
        *(float4*)(O + (size_t)t*Hh + h*Dd + tx*8)     = o1;
        *(float4*)(O + (size_t)t*Hh + h*Dd + tx*8 + 4) = o2;
    }
}

// ---------------- router (top-2 of 8 experts; outputs via device symbols) ----------------
__global__ void zero_counts() { if (threadIdx.x < Ee) g_ecount[threadIdx.x] = 0; }

__global__ __launch_bounds__(256) void router_kernel(
    const float* __restrict__ x, const float* __restrict__ rw)
{
    int t = blockIdx.x;
    const float* xr = x + (size_t)t*Hh;
    float acc[Ee];
    #pragma unroll
    for (int e = 0; e < Ee; e++) acc[e] = 0.f;
    for (int hh = threadIdx.x; hh < Hh; hh += 256) {
        float xv = xr[hh];
        #pragma unroll
        for (int e = 0; e < Ee; e++) acc[e] += xv * rw[e*Hh + hh];
    }
    #pragma unroll
    for (int e = 0; e < Ee; e++)
        #pragma unroll
        for (int o = 16; o > 0; o >>= 1) acc[e] += __shfl_xor_sync(0xffffffffu, acc[e], o);
    __shared__ float red[8][Ee];
    int warp = threadIdx.x >> 5, lane = threadIdx.x & 31;
    if (lane == 0)
        for (int e = 0; e < Ee; e++) red[warp][e] = acc[e];
    __syncthreads();
    if (threadIdx.x == 0) {
        float l[Ee];
        for (int e = 0; e < Ee; e++) {
            float ssum = 0.f;
            for (int w = 0; w < 8; w++) ssum += red[w][e];
            l[e] = ssum;
        }
        int i1 = 0;
        for (int e = 1; e < Ee; e++) if (l[e] > l[i1]) i1 = e;
        int i2 = -1;
        for (int e = 0; e < Ee; e++) if (e != i1 && (i2 < 0 || l[e] > l[i2])) i2 = e;
        float w1 = 1.f / (1.f + expf(l[i2] - l[i1]));
        g_rwflat[2*t]   = w1;
        g_rwflat[2*t+1] = 1.f - w1;
        int p1 = atomicAdd(&g_ecount[i1], 1); g_elist[i1*Tt + p1] = 2*t;
        int p2 = atomicAdd(&g_ecount[i2], 1); g_elist[i2*Tt + p2] = 2*t + 1;
    }
}

// ---------------- elementwise ----------------
__global__ void swiglu_moe_kernel(float* __restrict__ gb, const float* __restrict__ ub)
{
    int idx = blockIdx.x*256 + threadIdx.x;     // < 8*4096*512
    int e = idx >> 21;
    int r = (idx >> 9) & 4095;
    if (r >= g_ecount[e]) return;
    float g = gb[idx], u = ub[idx];
    gb[idx] = g * u / (1.f + expf(-g));
}

__global__ void swiglu_shared_kernel(const float* __restrict__ shg, float* __restrict__ sha)
{
    int idx = blockIdx.x*256 + threadIdx.x;     // < 4096*1024
    int t = idx >> 10;
    int i = idx & 1023;
    float a = shg[(size_t)t*2*ISH + i];
    float b = shg[(size_t)t*2*ISH + ISH + i];
    sha[idx] = a * b / (1.f + expf(-a));
}

__global__ void combine_kernel(const float* __restrict__ hid,
                               const float* __restrict__ yd,
                               const float* __restrict__ shr,
                               float* __restrict__ out)
{
    int idx = blockIdx.x*256 + threadIdx.x;     // < 4096*1536
    int t = idx / Hh;
    int c = idx - t*Hh;
    float mo = g_rwflat[2*t]   * yd[(size_t)(2*t)*Hh + c]
             + g_rwflat[2*t+1] * yd[(size_t)(2*t+1)*Hh + c];
    out[idx] = hid[idx] + RESMf * (mo + shr[idx]);
}

// ---------------- launch ----------------
extern "C" void kernel_launch(void* const* d_in, const int* in_sizes, int n_in,
                              void* d_out, int out_size)
{
    const float* hidden    = (const float*)d_in[0];
    const int*   pos       = (const int*)  d_in[1];
    const float* cosb      = (const float*)d_in[2];
    const float* sinb      = (const float*)d_in[3];
    const float* ln1       = (const float*)d_in[4];
    const float* ln2       = (const float*)d_in[5];
    const float* wq        = (const float*)d_in[6];
    const float* wk        = (const float*)d_in[7];
    const float* wv        = (const float*)d_in[8];
    const float* wo        = (const float*)d_in[9];
    const float* router_w  = (const float*)d_in[10];
    const float* w_gate    = (const float*)d_in[11];
    const float* w_up      = (const float*)d_in[12];
    const float* w_down    = (const float*)d_in[13];
    const float* shared_in = (const float*)d_in[14];
    const float* shared_ot = (const float*)d_in[15];
    float* out = (float*)d_out;

    // CRITICAL FIX: resolve REAL device addresses of __device__ scratch.
    // (Passing the symbols directly from host passes the host-shadow address,
    //  which GB300's ATS silently honors as host memory — the round-1..9 bug.)
    float *p_xnorm, *p_q, *p_k, *p_v, *p_attn, *p_hidden, *p_x2;
    float *p_shg, *p_shh, *p_shared, *p_gbuf, *p_ubuf, *p_ydown;
    cudaGetSymbolAddress((void**)&p_xnorm,  g_xnorm);
    cudaGetSymbolAddress((void**)&p_q,      g_q);
    cudaGetSymbolAddress((void**)&p_k,      g_k);
    cudaGetSymbolAddress((void**)&p_v,      g_v);
    cudaGetSymbolAddress((void**)&p_attn,   g_attn);
    cudaGetSymbolAddress((void**)&p_hidden, g_hidden);
    cudaGetSymbolAddress((void**)&p_x2,     g_x2);
    cudaGetSymbolAddress((void**)&p_shg,    g_shgate);
    cudaGetSymbolAddress((void**)&p_shh,    g_shh);
    cudaGetSymbolAddress((void**)&p_shared, g_shared);
    cudaGetSymbolAddress((void**)&p_gbuf,   g_gbuf);
    cudaGetSymbolAddress((void**)&p_ubuf,   g_ubuf);
    cudaGetSymbolAddress((void**)&p_ydown,  g_ydown);

    // ---- attention block ----
    rmsnorm_kernel<<<Tt, 256>>>(hidden, ln1, p_xnorm);
    gemm_tn<<<dim3(12,32), 256>>>(p_xnorm, Hh, wq, Hh, p_q, Hh, Tt, Hh, Hh, 1.f, nullptr);
    gemm_tn<<<dim3(4,32),  256>>>(p_xnorm, Hh, wk, Hh, p_k, NKVh*Dd, Tt, NKVh*Dd, Hh, 1.f, nullptr);
    gemm_tn<<<dim3(4,32),  256>>>(p_xnorm, Hh, wv, Hh, p_v, NKVh*Dd, Tt, NKVh*Dd, Hh, 1.f, nullptr);
    rope_kernel<<<(Tt*NHq*64 + 255)/256, 256>>>(p_q, NHq, pos, cosb, sinb);
    rope_kernel<<<(Tt*NKVh*64 + 255)/256, 256>>>(p_k, NKVh, pos, cosb, sinb);
    attn_kernel<<<dim3(64, NHq, Bb), 256>>>(p_q, p_k, p_v, p_attn);
    gemm_tn<<<dim3(12,32), 256>>>(p_attn, Hh, wo, Hh, p_hidden, Hh, Tt, Hh, Hh, RESMf, hidden);

    // ---- MoE + shared MLP block ----
    rmsnorm_kernel<<<Tt, 256>>>(p_hidden, ln2, p_x2);
    zero_counts<<<1, 32>>>();
    router_kernel<<<Tt, 256>>>(p_x2, router_w);
    gemm_tn<<<dim3(16,32), 256>>>(p_x2, Hh, shared_in, Hh, p_shg, 2*ISH, Tt, 2*ISH, Hh, 1.f, nullptr);
    moe_gemm<<<dim3(4,32,Ee), 256>>>(p_x2, Hh, w_gate, IEXP, Hh, p_gbuf, IEXP, 1, 0);
    moe_gemm<<<dim3(4,32,Ee), 256>>>(p_x2, Hh, w_up,   IEXP, Hh, p_ubuf, IEXP, 1, 0);
    swiglu_moe_kernel<<<(Ee*Tt*IEXP)/256, 256>>>(p_gbuf, p_ubuf);
    moe_gemm<<<dim3(12,32,Ee), 256>>>(p_gbuf, IEXP, w_down, Hh, IEXP, p_ydown, Hh, 0, 1);
    swiglu_shared_kernel<<<(Tt*ISH)/256, 256>>>(p_shg, p_shh);
    gemm_tn<<<dim3(12,32), 256>>>(p_shh, ISH, shared_ot, ISH, p_shared, Hh, Tt, Hh, ISH, 1.f, nullptr);
    combine_kernel<<<(Tt*Hh)/256, 256>>>(p_hidden, p_ydown, p_shared, out);
}

// round 11
// speedup vs baseline: 1.1442x; 1.1442x over previous
#include <cuda_runtime.h>
#include <cstdint>

// ---------------- problem constants ----------------
#define Bb 2
#define Ss 2048
#define Hh 1536
#define NHq 12
#define NKVh 4
#define Dd 128
#define Tt (Bb*Ss)          // 4096
#define Ee 8
#define IEXP 512
#define ISH 1024
#define SCALEf 0.0078125f
#define RESMf 0.22f
#define EPSf 1e-6f

// ---------------- scratch (device globals; addresses via cudaGetSymbolAddress) ----------------
__device__ float g_xnorm [Tt*Hh];
__device__ float g_q     [Tt*Hh];
__device__ float g_k     [Tt*NKVh*Dd];
__device__ float g_v     [Tt*NKVh*Dd];
__device__ float g_attn  [Tt*Hh];
__device__ float g_hidden[Tt*Hh];
__device__ float g_x2    [Tt*Hh];
__device__ float g_shgate[Tt*2*ISH];
__device__ float g_shh   [Tt*ISH];
__device__ float g_shared[Tt*Hh];
__device__ float g_gbuf  [Ee*Tt*IEXP];
__device__ float g_ubuf  [Ee*Tt*IEXP];
__device__ float g_ydown [Tt*2*Hh];
__device__ int   g_elist [Ee*Tt];
__device__ int   g_ecount[Ee];
__device__ float g_rwflat[Tt*2];

// ---------------- double-buffered 128x128x16 GEMM core ----------------
// a0/a1: per-thread A row pointers (row, row+64); may be null (zero rows).
// b0/b1: per-thread B row pointers (never null).
__device__ __forceinline__ void gemm_db(
    float (&As)[2][16][128], float (&Bs)[2][16][128],
    const float* a0, const float* a1,
    const float* b0, const float* b1,
    int K, int row, int kq, int tx, int ty,
    float (&acc)[8][8])
{
    const float4 z = make_float4(0.f,0.f,0.f,0.f);
    float4 av0, av1, bv0, bv1;

    av0 = a0 ? *(const float4*)(a0 + kq) : z;
    av1 = a1 ? *(const float4*)(a1 + kq) : z;
    bv0 = *(const float4*)(b0 + kq);
    bv1 = *(const float4*)(b1 + kq);
    As[0][kq+0][row]=av0.x; As[0][kq+1][row]=av0.y; As[0][kq+2][row]=av0.z; As[0][kq+3][row]=av0.w;
    As[0][kq+0][row+64]=av1.x; As[0][kq+1][row+64]=av1.y; As[0][kq+2][row+64]=av1.z; As[0][kq+3][row+64]=av1.w;
    Bs[0][kq+0][row]=bv0.x; Bs[0][kq+1][row]=bv0.y; Bs[0][kq+2][row]=bv0.z; Bs[0][kq+3][row]=bv0.w;
    Bs[0][kq+0][row+64]=bv1.x; Bs[0][kq+1][row+64]=bv1.y; Bs[0][kq+2][row+64]=bv1.z; Bs[0][kq+3][row+64]=bv1.w;
    __syncthreads();

    int cur = 0;
    for (int k0 = 16; k0 < K; k0 += 16) {
        av0 = a0 ? *(const float4*)(a0 + k0 + kq) : z;
        av1 = a1 ? *(const float4*)(a1 + k0 + kq) : z;
        bv0 = *(const float4*)(b0 + k0 + kq);
        bv1 = *(const float4*)(b1 + k0 + kq);
        #pragma unroll
        for (int kk = 0; kk < 16; kk++) {
            float a[8], b[8];
            *(float4*)&a[0] = *(const float4*)&As[cur][kk][ty*8];
            *(float4*)&a[4] = *(const float4*)&As[cur][kk][ty*8+4];
            *(float4*)&b[0] = *(const float4*)&Bs[cur][kk][tx*8];
            *(float4*)&b[4] = *(const float4*)&Bs[cur][kk][tx*8+4];
            #pragma unroll
            for (int i = 0; i < 8; i++)
                #pragma unroll
                for (int j = 0; j < 8; j++) acc[i][j] += a[i]*b[j];
        }
        int nxt = cur ^ 1;
        As[nxt][kq+0][row]=av0.x; As[nxt][kq+1][row]=av0.y; As[nxt][kq+2][row]=av0.z; As[nxt][kq+3][row]=av0.w;
        As[nxt][kq+0][row+64]=av1.x; As[nxt][kq+1][row+64]=av1.y; As[nxt][kq+2][row+64]=av1.z; As[nxt][kq+3][row+64]=av1.w;
        Bs[nxt][kq+0][row]=bv0.x; Bs[nxt][kq+1][row]=bv0.y; Bs[nxt][kq+2][row]=bv0.z; Bs[nxt][kq+3][row]=bv0.w;
        Bs[nxt][kq+0][row+64]=bv1.x; Bs[nxt][kq+1][row+64]=bv1.y; Bs[nxt][kq+2][row+64]=bv1.z; Bs[nxt][kq+3][row+64]=bv1.w;
        __syncthreads();
        cur = nxt;
    }
    #pragma unroll
    for (int kk = 0; kk < 16; kk++) {
        float a[8], b[8];
        *(float4*)&a[0] = *(const float4*)&As[cur][kk][ty*8];
        *(float4*)&a[4] = *(const float4*)&As[cur][kk][ty*8+4];
        *(float4*)&b[0] = *(const float4*)&Bs[cur][kk][tx*8];
        *(float4*)&b[4] = *(const float4*)&Bs[cur][kk][tx*8+4];
        #pragma unroll
        for (int i = 0; i < 8; i++)
            #pragma unroll
            for (int j = 0; j < 8; j++) acc[i][j] += a[i]*b[j];
    }
}

// ---------------- generic TN GEMM (all dims multiples of 128; M=4096) ----------------
__global__ void __launch_bounds__(256, 2) gemm_tn(
    const float* __restrict__ A, int lda,
    const float* __restrict__ B, int ldb,
    float* __restrict__ C, int ldc,
    int K, float alpha, const float* __restrict__ res)
{
    __shared__ __align__(16) float As[2][16][128];
    __shared__ __align__(16) float Bs[2][16][128];
    const int tid = threadIdx.x;
    const int m0 = blockIdx.y*128, n0 = blockIdx.x*128;
    const int row = tid>>2, kq = (tid&3)<<2, tx = tid&15, ty = tid>>4;
    const float* a0 = A + (size_t)(m0+row)*lda;
    const float* a1 = a0 + (size_t)64*lda;
    const float* b0 = B + (size_t)(n0+row)*ldb;
    const float* b1 = b0 + (size_t)64*ldb;
    float acc[8][8];
    #pragma unroll
    for (int i=0;i<8;i++)
        #pragma unroll
        for (int j=0;j<8;j++) acc[i][j]=0.f;

    gemm_db(As, Bs, a0, a1, b0, b1, K, row, kq, tx, ty, acc);

    #pragma unroll
    for (int i = 0; i < 8; i++) {
        int gm = m0 + ty*8 + i;
        #pragma unroll
        for (int j = 0; j < 8; j += 4) {
            int gn = n0 + tx*8 + j;
            float4 o;
            o.x = alpha*acc[i][j+0]; o.y = alpha*acc[i][j+1];
            o.z = alpha*acc[i][j+2]; o.w = alpha*acc[i][j+3];
            if (res) {
                float4 r = *(const float4*)(res + (size_t)gm*ldc + gn);
                o.x += r.x; o.y += r.y; o.z += r.z; o.w += r.w;
            }
            *(float4*)(C + (size_t)gm*ldc + gn) = o;
        }
    }
}

// ---------------- fused QKV GEMM: grid.x = 12(q)+4(k)+4(v) = 20 ----------------
__global__ void __launch_bounds__(256, 2) qkv_gemm(
    const float* __restrict__ A,
    const float* __restrict__ wq, const float* __restrict__ wk, const float* __restrict__ wv,
    float* __restrict__ q, float* __restrict__ k, float* __restrict__ v)
{
    __shared__ __align__(16) float As[2][16][128];
    __shared__ __align__(16) float Bs[2][16][128];
    const int bx = blockIdx.x;
    const float* B; float* C; int ldc, n0;
    if (bx < 12)      { B = wq; C = q; ldc = Hh;       n0 = bx*128; }
    else if (bx < 16) { B = wk; C = k; ldc = NKVh*Dd;  n0 = (bx-12)*128; }
    else              { B = wv; C = v; ldc = NKVh*Dd;  n0 = (bx-16)*128; }

    const int tid = threadIdx.x;
    const int m0 = blockIdx.y*128;
    const int row = tid>>2, kq = (tid&3)<<2, tx = tid&15, ty = tid>>4;
    const float* a0 = A + (size_t)(m0+row)*Hh;
    const float* a1 = a0 + (size_t)64*Hh;
    const float* b0 = B + (size_t)(n0+row)*Hh;
    const float* b1 = b0 + (size_t)64*Hh;
    float acc[8][8];
    #pragma unroll
    for (int i=0;i<8;i++)
        #pragma unroll
        for (int j=0;j<8;j++) acc[i][j]=0.f;

    gemm_db(As, Bs, a0, a1, b0, b1, Hh, row, kq, tx, ty, acc);

    #pragma unroll
    for (int i = 0; i < 8; i++) {
        int gm = m0 + ty*8 + i;
        #pragma unroll
        for (int j = 0; j < 8; j += 4) {
            int gn = n0 + tx*8 + j;
            float4 o;
            o.x = acc[i][j+0]; o.y = acc[i][j+1]; o.z = acc[i][j+2]; o.w = acc[i][j+3];
            *(float4*)(C + (size_t)gm*ldc + gn) = o;
        }
    }
}

// ---------------- fused MoE gate+up GEMM (gathered rows): grid.x = 4+4, grid.z = E ----------------
__global__ void __launch_bounds__(256, 2) moe_gu_gemm(
    const float* __restrict__ X,
    const float* __restrict__ w_gate, const float* __restrict__ w_up,
    float* __restrict__ gbuf, float* __restrict__ ubuf)
{
    const int e = blockIdx.z;
    const int count = g_ecount[e];
    const int m0 = blockIdx.y*128;
    if (m0 >= count) return;
    const int bx = blockIdx.x;
    const float* B = (bx < 4 ? w_gate : w_up) + (size_t)e*IEXP*Hh;
    float* C = (bx < 4 ? gbuf : ubuf);
    const int n0 = (bx & 3)*128;

    __shared__ __align__(16) float As[2][16][128];
    __shared__ __align__(16) float Bs[2][16][128];
    __shared__ int rowmap[128];
    const int tid = threadIdx.x;
    const int row = tid>>2, kq = (tid&3)<<2, tx = tid&15, ty = tid>>4;
    if (tid < 128) {
        int r = m0 + tid;
        rowmap[tid] = (r < count) ? (g_elist[e*Tt + r] >> 1) : -1;
    }
    __syncthreads();
    int s0 = rowmap[row], s1 = rowmap[row+64];
    const float* a0 = (s0 >= 0) ? X + (size_t)s0*Hh : nullptr;
    const float* a1 = (s1 >= 0) ? X + (size_t)s1*Hh : nullptr;
    const float* b0 = B + (size_t)(n0+row)*Hh;
    const float* b1 = b0 + (size_t)64*Hh;
    float acc[8][8];
    #pragma unroll
    for (int i=0;i<8;i++)
        #pragma unroll
        for (int j=0;j<8;j++) acc[i][j]=0.f;

    gemm_db(As, Bs, a0, a1, b0, b1, Hh, row, kq, tx, ty, acc);

    #pragma unroll
    for (int i = 0; i < 8; i++) {
        int r = m0 + ty*8 + i;
        if (r >= count) continue;
        #pragma unroll
        for (int j = 0; j < 8; j += 4) {
            int gn = n0 + tx*8 + j;
            float4 o;
            o.x = acc[i][j+0]; o.y = acc[i][j+1]; o.z = acc[i][j+2]; o.w = acc[i][j+3];
            *(float4*)(C + ((size_t)e*Tt + r)*IEXP + gn) = o;
        }
    }
}

// ---------------- MoE down GEMM (scatter rows): grid.x = 12, grid.z = E ----------------
__global__ void __launch_bounds__(256, 2) moe_down_gemm(
    const float* __restrict__ Gact,     // [E][Tt][IEXP], padded-slot rows
    const float* __restrict__ w_down,
    float* __restrict__ ydown)          // [2T][Hh], scattered by g_elist
{
    const int e = blockIdx.z;
    const int count = g_ecount[e];
    const int m0 = blockIdx.y*128;
    if (m0 >= count) return;
    const float* B = w_down + (size_t)e*Hh*IEXP;
    const int n0 = blockIdx.x*128;

    __shared__ __align__(16) float As[2][16][128];
    __shared__ __align__(16) float Bs[2][16][128];
    const int tid = threadIdx.x;
    const int row = tid>>2, kq = (tid&3)<<2, tx = tid&15, ty = tid>>4;
    const float* a0 = Gact + ((size_t)e*Tt + m0 + row)*IEXP;
    const float* a1 = a0 + (size_t)64*IEXP;
    const float* b0 = B + (size_t)(n0+row)*IEXP;
    const float* b1 = b0 + (size_t)64*IEXP;
    float acc[8][8];
    #pragma unroll
    for (int i=0;i<8;i++)
        #pragma unroll
        for (int j=0;j<8;j++) acc[i][j]=0.f;

    gemm_db(As, Bs, a0, a1, b0, b1, IEXP, row, kq, tx, ty, acc);

    const int* lst = g_elist + e*Tt;
    #pragma unroll
    for (int i = 0; i < 8; i++) {
        int r = m0 + ty*8 + i;
        if (r >= count) continue;
        int orow = lst[r];
        #pragma unroll
        for (int j = 0; j < 8; j += 4) {
            int gn = n0 + tx*8 + j;
            float4 o;
            o.x = acc[i][j+0]; o.y = acc[i][j+1]; o.z = acc[i][j+2]; o.w = acc[i][j+3];
            *(float4*)(ydown + (size_t)orow*Hh + gn) = o;
        }
    }
}

// ---------------- rmsnorm ----------------
__global__ __launch_bounds__(256) void rmsnorm_kernel(
    const float* __restrict__ x, const float* __restrict__ w, float* __restrict__ y)
{
    int t = blockIdx.x;
    const float* xr = x + (size_t)t*Hh;
    float s = 0.f;
    for (int i = threadIdx.x; i < Hh; i += 256) { float v = xr[i]; s += v*v; }
    #pragma unroll
    for (int o = 16; o > 0; o >>= 1) s += __shfl_xor_sync(0xffffffffu, s, o);
    __shared__ float red[8];
    if ((threadIdx.x & 31) == 0) red[threadIdx.x >> 5] = s;
    __syncthreads();
    float tot = 0.f;
    #pragma unroll
    for (int wv = 0; wv < 8; wv++) tot += red[wv];
    float inv = rsqrtf(tot * (1.0f/(float)Hh) + EPSf);
    float* yr = y + (size_t)t*Hh;
    for (int i = threadIdx.x; i < Hh; i += 256) yr[i] = w[i]*xr[i]*inv;
}

// ---------------- RoPE ----------------
__global__ void rope_kernel(float* __restrict__ a, int nheads,
                            const int* __restrict__ pos_ids,
                            const float* __restrict__ cosb,
                            const float* __restrict__ sinb)
{
    int idx = blockIdx.x*256 + threadIdx.x;
    int total = Tt * nheads * 64;
    if (idx >= total) return;
    int dd = idx & 63;
    int hh = (idx >> 6) % nheads;
    int t  = idx / (64*nheads);
    int pos = pos_ids[t] & 4095;
    float c1 = cosb[pos*Dd + dd],      s1 = sinb[pos*Dd + dd];
    float c2 = cosb[pos*Dd + dd + 64], s2 = sinb[pos*Dd + dd + 64];
    float* base = a + (size_t)t*(nheads*Dd) + hh*Dd;
    float x1 = base[dd], x2 = base[dd+64];
    base[dd]     = x1*c1 - x2*s1;
    base[dd+64]  = x2*c2 + x1*s2;
}

// ---------------- flash attention, 32x32 tiles, static smem ----------------
__global__ __launch_bounds__(256) void attn_kernel(
    const float* __restrict__ Q, const float* __restrict__ Kg,
    const float* __restrict__ Vg, float* __restrict__ O)
{
    __shared__ float Qt[128][33];
    __shared__ float KV[128*33];
    __shared__ float Pt[32][33];
    int qt = blockIdx.x, h = blockIdx.y, b = blockIdx.z;
    int kvh = h / (NHq/NKVh);
    int tid = threadIdx.x;
    int tx = tid & 15, ty = tid >> 4;
    int tq0 = b*Ss + qt*32;

    #pragma unroll
    for (int i = 0; i < 4; i++) {
        int v = tid + i*256;
        int r = v >> 5;
        int dq = (v & 31) << 2;
        float4 qv = *(const float4*)(Q + (size_t)(tq0+r)*Hh + h*Dd + dq);
        Qt[dq+0][r] = qv.x * SCALEf;
        Qt[dq+1][r] = qv.y * SCALEf;
        Qt[dq+2][r] = qv.z * SCALEf;
        Qt[dq+3][r] = qv.w * SCALEf;
    }

    float m_i[2], l_i[2], acc[2][8];
    #pragma unroll
    for (int i = 0; i < 2; i++) {
        m_i[i] = -1e30f; l_i[i] = 0.f;
        #pragma unroll
        for (int j = 0; j < 8; j++) acc[i][j] = 0.f;
    }

    for (int kt = 0; kt <= qt; kt++) {
        int tk0 = b*Ss + kt*32;
        __syncthreads();
        #pragma unroll
        for (int i = 0; i < 4; i++) {
            int v = tid + i*256;
            int r = v >> 5;
            int dq = (v & 31) << 2;
            float4 kv = *(const float4*)(Kg + (size_t)(tk0+r)*(NKVh*Dd) + kvh*Dd + dq);
            KV[(dq+0)*33 + r] = kv.x; KV[(dq+1)*33 + r] = kv.y;
            KV[(dq+2)*33 + r] = kv.z; KV[(dq+3)*33 + r] = kv.w;
        }
        __syncthreads();

        float s[2][2];
        s[0][0]=s[0][1]=s[1][0]=s[1][1]=0.f;
        for (int d = 0; d < 128; d++) {
            float a0 = Qt[d][ty*2+0], a1 = Qt[d][ty*2+1];
            float b0 = KV[d*33 + tx*2+0], b1 = KV[d*33 + tx*2+1];
            s[0][0] += a0*b0; s[0][1] += a0*b1;
            s[1][0] += a1*b0; s[1][1] += a1*b1;
        }
        if (kt == qt) {
            #pragma unroll
            for (int i = 0; i < 2; i++)
                #pragma unroll
                for (int j = 0; j < 2; j++)
                    if (tx*2 + j > ty*2 + i) s[i][j] = -1e30f;
        }
        #pragma unroll
        for (int i = 0; i < 2; i++) {
            float mx = fmaxf(s[i][0], s[i][1]);
            #pragma unroll
            for (int o = 1; o < 16; o <<= 1) mx = fmaxf(mx, __shfl_xor_sync(0xffffffffu, mx, o));
            float mn = fmaxf(m_i[i], mx);
            float p0 = __expf(s[i][0] - mn);
            float p1 = __expf(s[i][1] - mn);
            float psum = p0 + p1;
            #pragma unroll
            for (int o = 1; o < 16; o <<= 1) psum += __shfl_xor_sync(0xffffffffu, psum, o);
            float f = __expf(m_i[i] - mn);
            l_i[i] = l_i[i]*f + psum;
            m_i[i] = mn;
            #pragma unroll
            for (int j = 0; j < 8; j++) acc[i][j] *= f;
            Pt[tx*2+0][ty*2+i] = p0;
            Pt[tx*2+1][ty*2+i] = p1;
        }
        __syncthreads();
        #pragma unroll
        for (int i = 0; i < 4; i++) {
            int v = tid + i*256;
            int r = v >> 5;
            int dq = (v & 31) << 2;
            float4 vv = *(const float4*)(Vg + (size_t)(tk0+r)*(NKVh*Dd) + kvh*Dd + dq);
            *(float4*)(KV + r*128 + dq) = vv;
        }
        __syncthreads();
        for (int k = 0; k < 32; k++) {
            float a0 = Pt[k][ty*2+0], a1 = Pt[k][ty*2+1];
            float bb[8];
            *(float4*)&bb[0] = *(const float4*)(KV + k*128 + tx*8);
            *(float4*)&bb[4] = *(const float4*)(KV + k*128 + tx*8 + 4);
            #pragma unroll
            for (int j = 0; j < 8; j++) {
                acc[0][j] += a0*bb[j];
                acc[1][j] += a1*bb[j];
            }
        }
    }
    #pragma unroll
    for (int i = 0; i < 2; i++) {
        float inv = 1.0f / l_i[i];
        int t = tq0 + ty*2 + i;
        float4 o1, o2;
        o1.x = acc[i][0]*inv; o1.y = acc[i][1]*inv; o1.z = acc[i][2]*inv; o1.w = acc[i][3]*inv;
        o2.x = acc[i][4]*inv; o2.y = acc[i][5]*inv; o2.z = acc[i][6]*inv; o2.w = acc[i][7]*inv;
        *(float4*)(O + (size_t)t*Hh + h*Dd + tx*8)     = o1;
        *(float4*)(O + (size_t)t*Hh + h*Dd + tx*8 + 4) = o2;
    }
}

// ---------------- router ----------------
__global__ void zero_counts() { if (threadIdx.x < Ee) g_ecount[threadIdx.x] = 0; }

__global__ __launch_bounds__(256) void router_kernel(
    const float* __restrict__ x, const float* __restrict__ rw)
{
    int t = blockIdx.x;
    const float* xr = x + (size_t)t*Hh;
    float acc[Ee];
    #pragma unroll
    for (int e = 0; e < Ee; e++) acc[e] = 0.f;
    for (int hh = threadIdx.x; hh < Hh; hh += 256) {
        float xv = xr[hh];
        #pragma unroll
        for (int e = 0; e < Ee; e++) acc[e] += xv * rw[e*Hh + hh];
    }
    #pragma unroll
    for (int e = 0; e < Ee; e++)
        #pragma unroll
        for (int o = 16; o > 0; o >>= 1) acc[e] += __shfl_xor_sync(0xffffffffu, acc[e], o);
    __shared__ float red[8][Ee];
    int warp = threadIdx.x >> 5, lane = threadIdx.x & 31;
    if (lane == 0)
        for (int e = 0; e < Ee; e++) red[warp][e] = acc[e];
    __syncthreads();
    if (threadIdx.x == 0) {
        float l[Ee];
        for (int e = 0; e < Ee; e++) {
            float ssum = 0.f;
            for (int w = 0; w < 8; w++) ssum += red[w][e];
            l[e] = ssum;
        }
        int i1 = 0;
        for (int e = 1; e < Ee; e++) if (l[e] > l[i1]) i1 = e;
        int i2 = -1;
        for (int e = 0; e < Ee; e++) if (e != i1 && (i2 < 0 || l[e] > l[i2])) i2 = e;
        float w1 = 1.f / (1.f + __expf(l[i2] - l[i1]));
        g_rwflat[2*t]   = w1;
        g_rwflat[2*t+1] = 1.f - w1;
        int p1 = atomicAdd(&g_ecount[i1], 1); g_elist[i1*Tt + p1] = 2*t;
        int p2 = atomicAdd(&g_ecount[i2], 1); g_elist[i2*Tt + p2] = 2*t + 1;
    }
}

// ---------------- elementwise ----------------
__global__ void swiglu_moe_kernel(float* __restrict__ gb, const float* __restrict__ ub)
{
    int idx = blockIdx.x*256 + threadIdx.x;
    int e = idx >> 21;
    int r = (idx >> 9) & 4095;
    if (r >= g_ecount[e]) return;
    float g = gb[idx], u = ub[idx];
    gb[idx] = g * u / (1.f + __expf(-g));
}

__global__ void swiglu_shared_kernel(const float* __restrict__ shg, float* __restrict__ sha)
{
    int idx = blockIdx.x*256 + threadIdx.x;
    int t = idx >> 10;
    int i = idx & 1023;
    float a = shg[(size_t)t*2*ISH + i];
    float b = shg[(size_t)t*2*ISH + ISH + i];
    sha[idx] = a * b / (1.f + __expf(-a));
}

__global__ void combine_kernel(const float* __restrict__ hid,
                               const float* __restrict__ yd,
                               const float* __restrict__ shr,
                               float* __restrict__ out)
{
    int idx = blockIdx.x*256 + threadIdx.x;
    int t = idx / Hh;
    int c = idx - t*Hh;
    float mo = g_rwflat[2*t]   * yd[(size_t)(2*t)*Hh + c]
             + g_rwflat[2*t+1] * yd[(size_t)(2*t+1)*Hh + c];
    out[idx] = hid[idx] + RESMf * (mo + shr[idx]);
}

// ---------------- launch ----------------
extern "C" void kernel_launch(void* const* d_in, const int* in_sizes, int n_in,
                              void* d_out, int out_size)
{
    const float* hidden    = (const float*)d_in[0];
    const int*   pos       = (const int*)  d_in[1];
    const float* cosb      = (const float*)d_in[2];
    const float* sinb      = (const float*)d_in[3];
    const float* ln1       = (const float*)d_in[4];
    const float* ln2       = (const float*)d_in[5];
    const float* wq        = (const float*)d_in[6];
    const float* wk        = (const float*)d_in[7];
    const float* wv        = (const float*)d_in[8];
    const float* wo        = (const float*)d_in[9];
    const float* router_w  = (const float*)d_in[10];
    const float* w_gate    = (const float*)d_in[11];
    const float* w_up      = (const float*)d_in[12];
    const float* w_down    = (const float*)d_in[13];
    const float* shared_in = (const float*)d_in[14];
    const float* shared_ot = (const float*)d_in[15];
    float* out = (float*)d_out;

    float *p_xnorm, *p_q, *p_k, *p_v, *p_attn, *p_hidden, *p_x2;
    float *p_shg, *p_shh, *p_shared, *p_gbuf, *p_ubuf, *p_ydown;
    cudaGetSymbolAddress((void**)&p_xnorm,  g_xnorm);
    cudaGetSymbolAddress((void**)&p_q,      g_q);
    cudaGetSymbolAddress((void**)&p_k,      g_k);
    cudaGetSymbolAddress((void**)&p_v,      g_v);
    cudaGetSymbolAddress((void**)&p_attn,   g_attn);
    cudaGetSymbolAddress((void**)&p_hidden, g_hidden);
    cudaGetSymbolAddress((void**)&p_x2,     g_x2);
    cudaGetSymbolAddress((void**)&p_shg,    g_shgate);
    cudaGetSymbolAddress((void**)&p_shh,    g_shh);
    cudaGetSymbolAddress((void**)&p_shared, g_shared);
    cudaGetSymbolAddress((void**)&p_gbuf,   g_gbuf);
    cudaGetSymbolAddress((void**)&p_ubuf,   g_ubuf);
    cudaGetSymbolAddress((void**)&p_ydown,  g_ydown);

    // ---- attention block ----
    rmsnorm_kernel<<<Tt, 256>>>(hidden, ln1, p_xnorm);
    qkv_gemm<<<dim3(20,32), 256>>>(p_xnorm, wq, wk, wv, p_q, p_k, p_v);
    rope_kernel<<<(Tt*NHq*64 + 255)/256, 256>>>(p_q, NHq, pos, cosb, sinb);
    rope_kernel<<<(Tt*NKVh*64 + 255)/256, 256>>>(p_k, NKVh, pos, cosb, sinb);
    attn_kernel<<<dim3(64, NHq, Bb), 256>>>(p_q, p_k, p_v, p_attn);
    gemm_tn<<<dim3(12,32), 256>>>(p_attn, Hh, wo, Hh, p_hidden, Hh, Hh, RESMf, hidden);

    // ---- MoE + shared MLP block ----
    rmsnorm_kernel<<<Tt, 256>>>(p_hidden, ln2, p_x2);
    zero_counts<<<1, 32>>>();
    router_kernel<<<Tt, 256>>>(p_x2, router_w);
    gemm_tn<<<dim3(16,32), 256>>>(p_x2, Hh, shared_in, Hh, p_shg, 2*ISH, Hh, 1.f, nullptr);
    moe_gu_gemm<<<dim3(8,32,Ee), 256>>>(p_x2, w_gate, w_up, p_gbuf, p_ubuf);
    swiglu_moe_kernel<<<(Ee*Tt*IEXP)/256, 256>>>(p_gbuf, p_ubuf);
    moe_down_gemm<<<dim3(12,32,Ee), 256>>>(p_gbuf, w_down, p_ydown);
    swiglu_shared_kernel<<<(Tt*ISH)/256, 256>>>(p_shg, p_shh);
    gemm_tn<<<dim3(12,32), 256>>>(p_shh, ISH, shared_ot, ISH, p_shared, Hh, ISH, 1.f, nullptr);
    combine_kernel<<<(Tt*Hh)/256, 256>>>(p_hidden, p_ydown, p_shared, out);
}

// round 12
// speedup vs baseline: 1.8499x; 1.6167x over previous
#include <cuda_runtime.h>
#include <cstdint>

// ---------------- problem constants ----------------
#define Bb 2
#define Ss 2048
#define Hh 1536
#define NHq 12
#define NKVh 4
#define Dd 128
#define Tt (Bb*Ss)          // 4096
#define Ee 8
#define IEXP 512
#define ISH 1024
#define SCALEf 0.0078125f
#define RESMf 0.22f
#define EPSf 1e-6f

// ---------------- scratch (device globals; addresses via cudaGetSymbolAddress) ----------------
__device__ float g_xnorm [Tt*Hh];
__device__ float g_q     [Tt*Hh];
__device__ float g_k     [Tt*NKVh*Dd];
__device__ float g_v     [Tt*NKVh*Dd];
__device__ float g_attn  [Tt*Hh];
__device__ float g_hidden[Tt*Hh];
__device__ float g_x2    [Tt*Hh];
__device__ float g_shgate[Tt*2*ISH];
__device__ float g_shh   [Tt*ISH];
__device__ float g_shared[Tt*Hh];
__device__ float g_gbuf  [Ee*Tt*IEXP];
__device__ float g_ubuf  [Ee*Tt*IEXP];
__device__ float g_ydown [Tt*2*Hh];
__device__ int   g_elist [Ee*Tt];
__device__ int   g_ecount[Ee];
__device__ float g_rwflat[Tt*2];

// ---------------- tf32 helpers ----------------
__device__ __forceinline__ unsigned f2tf(float x)
{
    unsigned u;
    asm("cvt.rna.tf32.f32 %0, %1;" : "=r"(u) : "f"(x));
    return u;
}

struct SmemT {
    float As[2][128][36];
    float Bs[2][128][36];
};
#define SMEM_BYTES ((int)sizeof(SmemT))   // 73728

// 16 mma per warp per k8; warp tile 32x64 (wm in 0..3 rows, wn in 0..1 cols)
__device__ __forceinline__ void mma_compute(
    const float (&A)[128][36], const float (&B)[128][36],
    int lane, int wm, int wn, float (&acc)[2][8][4])
{
    const int g = lane >> 2, t = lane & 3;
    #pragma unroll
    for (int kk = 0; kk < 4; kk++) {
        const int kb = kk*8;
        unsigned af[2][4];
        #pragma unroll
        for (int mt = 0; mt < 2; mt++) {
            int ar = wm*32 + mt*16 + g;
            af[mt][0] = __float_as_uint(A[ar  ][kb+t  ]);
            af[mt][1] = __float_as_uint(A[ar+8][kb+t  ]);
            af[mt][2] = __float_as_uint(A[ar  ][kb+t+4]);
            af[mt][3] = __float_as_uint(A[ar+8][kb+t+4]);
        }
        #pragma unroll
        for (int nt = 0; nt < 8; nt++) {
            int br = wn*64 + nt*8 + g;
            unsigned b0 = __float_as_uint(B[br][kb+t  ]);
            unsigned b1 = __float_as_uint(B[br][kb+t+4]);
            #pragma unroll
            for (int mt = 0; mt < 2; mt++) {
                asm volatile(
                    "mma.sync.aligned.m16n8k8.row.col.f32.tf32.tf32.f32 "
                    "{%0,%1,%2,%3}, {%4,%5,%6,%7}, {%8,%9}, {%0,%1,%2,%3};"
                    : "+f"(acc[mt][nt][0]), "+f"(acc[mt][nt][1]),
                      "+f"(acc[mt][nt][2]), "+f"(acc[mt][nt][3])
                    : "r"(af[mt][0]), "r"(af[mt][1]), "r"(af[mt][2]), "r"(af[mt][3]),
                      "r"(b0), "r"(b1));
            }
        }
    }
}

// double-buffered K loop. ag: this thread's A row base (+half*16 cols), may be null.
// bg: this thread's B row base (+half*16). row = tid>>1, c0off = (tid&1)*16.
__device__ __forceinline__ void tf32_db(
    SmemT& S,
    const float* ag, const float* bg,
    int row, int c0off, int K,
    int lane, int wm, int wn,
    float (&acc)[2][8][4])
{
    // chunk 0
    #pragma unroll
    for (int i = 0; i < 4; i++) {
        float4 a = ag ? *(const float4*)(ag + i*4) : make_float4(0.f,0.f,0.f,0.f);
        float4 b = *(const float4*)(bg + i*4);
        S.As[0][row][c0off+i*4+0] = __uint_as_float(f2tf(a.x));
        S.As[0][row][c0off+i*4+1] = __uint_as_float(f2tf(a.y));
        S.As[0][row][c0off+i*4+2] = __uint_as_float(f2tf(a.z));
        S.As[0][row][c0off+i*4+3] = __uint_as_float(f2tf(a.w));
        S.Bs[0][row][c0off+i*4+0] = __uint_as_float(f2tf(b.x));
        S.Bs[0][row][c0off+i*4+1] = __uint_as_float(f2tf(b.y));
        S.Bs[0][row][c0off+i*4+2] = __uint_as_float(f2tf(b.z));
        S.Bs[0][row][c0off+i*4+3] = __uint_as_float(f2tf(b.w));
    }
    __syncthreads();

    int cur = 0;
    for (int k0 = 32; k0 < K; k0 += 32) {
        float4 an[4], bn[4];
        #pragma unroll
        for (int i = 0; i < 4; i++) {
            an[i] = ag ? *(const float4*)(ag + k0 + i*4) : make_float4(0.f,0.f,0.f,0.f);
            bn[i] = *(const float4*)(bg + k0 + i*4);
        }
        mma_compute(S.As[cur], S.Bs[cur], lane, wm, wn, acc);
        int nxt = cur ^ 1;
        #pragma unroll
        for (int i = 0; i < 4; i++) {
            S.As[nxt][row][c0off+i*4+0] = __uint_as_float(f2tf(an[i].x));
            S.As[nxt][row][c0off+i*4+1] = __uint_as_float(f2tf(an[i].y));
            S.As[nxt][row][c0off+i*4+2] = __uint_as_float(f2tf(an[i].z));
            S.As[nxt][row][c0off+i*4+3] = __uint_as_float(f2tf(an[i].w));
            S.Bs[nxt][row][c0off+i*4+0] = __uint_as_float(f2tf(bn[i].x));
            S.Bs[nxt][row][c0off+i*4+1] = __uint_as_float(f2tf(bn[i].y));
            S.Bs[nxt][row][c0off+i*4+2] = __uint_as_float(f2tf(bn[i].z));
            S.Bs[nxt][row][c0off+i*4+3] = __uint_as_float(f2tf(bn[i].w));
        }
        __syncthreads();
        cur = nxt;
    }
    mma_compute(S.As[cur], S.Bs[cur], lane, wm, wn, acc);
}

// ---------------- generic TN GEMM (tf32 tensor): C = alpha*A@B^T (+res) ----------------
__global__ void __launch_bounds__(256, 2) tc_gemm(
    const float* __restrict__ A, int lda,
    const float* __restrict__ B, int ldb,
    float* __restrict__ C, int ldc,
    int K, float alpha, const float* __restrict__ res)
{
    extern __shared__ char smemraw[];
    SmemT& S = *reinterpret_cast<SmemT*>(smemraw);
    const int tid = threadIdx.x, lane = tid & 31, warp = tid >> 5;
    const int wm = warp & 3, wn = warp >> 2;
    const int m0 = blockIdx.y*128, n0 = blockIdx.x*128;
    const int row = tid >> 1, c0off = (tid & 1)*16;
    const float* ag = A + (size_t)(m0+row)*lda + c0off;
    const float* bg = B + (size_t)(n0+row)*ldb + c0off;

    float acc[2][8][4];
    #pragma unroll
    for (int i=0;i<2;i++) for (int j=0;j<8;j++) for (int c=0;c<4;c++) acc[i][j][c]=0.f;

    tf32_db(S, ag, bg, row, c0off, K, lane, wm, wn, acc);

    const int g = lane >> 2, t = lane & 3;
    #pragma unroll
    for (int mt = 0; mt < 2; mt++) {
        int gm = m0 + wm*32 + mt*16 + g;
        #pragma unroll
        for (int nt = 0; nt < 8; nt++) {
            int gn = n0 + wn*64 + nt*8 + t*2;
            float2 v0, v1;
            v0.x = alpha*acc[mt][nt][0]; v0.y = alpha*acc[mt][nt][1];
            v1.x = alpha*acc[mt][nt][2]; v1.y = alpha*acc[mt][nt][3];
            if (res) {
                const float* r0 = res + (size_t)gm*ldc + gn;
                const float* r1 = res + (size_t)(gm+8)*ldc + gn;
                v0.x += r0[0]; v0.y += r0[1];
                v1.x += r1[0]; v1.y += r1[1];
            }
            *(float2*)(C + (size_t)gm*ldc + gn)     = v0;
            *(float2*)(C + (size_t)(gm+8)*ldc + gn) = v1;
        }
    }
}

// ---------------- fused QKV (tf32): grid.x = 12(q)+4(k)+4(v) ----------------
__global__ void __launch_bounds__(256, 2) tc_qkv(
    const float* __restrict__ A,
    const float* __restrict__ wq, const float* __restrict__ wk, const float* __restrict__ wv,
    float* __restrict__ q, float* __restrict__ k, float* __restrict__ v)
{
    extern __shared__ char smemraw[];
    SmemT& S = *reinterpret_cast<SmemT*>(smemraw);
    const int bx = blockIdx.x;
    const float* B; float* C; int ldc, n0;
    if (bx < 12)      { B = wq; C = q; ldc = Hh;      n0 = bx*128; }
    else if (bx < 16) { B = wk; C = k; ldc = NKVh*Dd; n0 = (bx-12)*128; }
    else              { B = wv; C = v; ldc = NKVh*Dd; n0 = (bx-16)*128; }

    const int tid = threadIdx.x, lane = tid & 31, warp = tid >> 5;
    const int wm = warp & 3, wn = warp >> 2;
    const int m0 = blockIdx.y*128;
    const int row = tid >> 1, c0off = (tid & 1)*16;
    const float* ag = A + (size_t)(m0+row)*Hh + c0off;
    const float* bg = B + (size_t)(n0+row)*Hh + c0off;

    float acc[2][8][4];
    #pragma unroll
    for (int i=0;i<2;i++) for (int j=0;j<8;j++) for (int c=0;c<4;c++) acc[i][j][c]=0.f;

    tf32_db(S, ag, bg, row, c0off, Hh, lane, wm, wn, acc);

    const int g = lane >> 2, t = lane & 3;
    #pragma unroll
    for (int mt = 0; mt < 2; mt++) {
        int gm = m0 + wm*32 + mt*16 + g;
        #pragma unroll
        for (int nt = 0; nt < 8; nt++) {
            int gn = n0 + wn*64 + nt*8 + t*2;
            float2 v0, v1;
            v0.x = acc[mt][nt][0]; v0.y = acc[mt][nt][1];
            v1.x = acc[mt][nt][2]; v1.y = acc[mt][nt][3];
            *(float2*)(C + (size_t)gm*ldc + gn)     = v0;
            *(float2*)(C + (size_t)(gm+8)*ldc + gn) = v1;
        }
    }
}

// ---------------- MoE gate+up (tf32, gathered rows): grid.x = 8, grid.z = E ----------------
__global__ void __launch_bounds__(256, 2) tc_moe_gu(
    const float* __restrict__ X,
    const float* __restrict__ w_gate, const float* __restrict__ w_up,
    float* __restrict__ gbuf, float* __restrict__ ubuf)
{
    const int e = blockIdx.z;
    const int count = g_ecount[e];
    const int m0 = blockIdx.y*128;
    if (m0 >= count) return;
    extern __shared__ char smemraw[];
    SmemT& S = *reinterpret_cast<SmemT*>(smemraw);
    __shared__ int rowmap[128];

    const int bx = blockIdx.x;
    const float* B = (bx < 4 ? w_gate : w_up) + (size_t)e*IEXP*Hh;
    float* C = (bx < 4 ? gbuf : ubuf);
    const int n0 = (bx & 3)*128;

    const int tid = threadIdx.x, lane = tid & 31, warp = tid >> 5;
    const int wm = warp & 3, wn = warp >> 2;
    const int row = tid >> 1, c0off = (tid & 1)*16;
    if (tid < 128) {
        int r = m0 + tid;
        rowmap[tid] = (r < count) ? (g_elist[e*Tt + r] >> 1) : -1;
    }
    __syncthreads();
    int src = rowmap[row];
    const float* ag = (src >= 0) ? X + (size_t)src*Hh + c0off : nullptr;
    const float* bg = B + (size_t)(n0+row)*Hh + c0off;

    float acc[2][8][4];
    #pragma unroll
    for (int i=0;i<2;i++) for (int j=0;j<8;j++) for (int c=0;c<4;c++) acc[i][j][c]=0.f;

    tf32_db(S, ag, bg, row, c0off, Hh, lane, wm, wn, acc);

    const int g = lane >> 2, t = lane & 3;
    #pragma unroll
    for (int mt = 0; mt < 2; mt++) {
        int r0 = m0 + wm*32 + mt*16 + g;
        #pragma unroll
        for (int nt = 0; nt < 8; nt++) {
            int gn = n0 + wn*64 + nt*8 + t*2;
            if (r0 < count) {
                float2 v; v.x = acc[mt][nt][0]; v.y = acc[mt][nt][1];
                *(float2*)(C + ((size_t)e*Tt + r0)*IEXP + gn) = v;
            }
            if (r0+8 < count) {
                float2 v; v.x = acc[mt][nt][2]; v.y = acc[mt][nt][3];
                *(float2*)(C + ((size_t)e*Tt + r0+8)*IEXP + gn) = v;
            }
        }
    }
}

// ---------------- MoE down (tf32, scatter rows): grid.x = 12, grid.z = E ----------------
__global__ void __launch_bounds__(256, 2) tc_moe_down(
    const float* __restrict__ Gact,
    const float* __restrict__ w_down,
    float* __restrict__ ydown)
{
    const int e = blockIdx.z;
    const int count = g_ecount[e];
    const int m0 = blockIdx.y*128;
    if (m0 >= count) return;
    extern __shared__ char smemraw[];
    SmemT& S = *reinterpret_cast<SmemT*>(smemraw);

    const float* B = w_down + (size_t)e*Hh*IEXP;
    const int n0 = blockIdx.x*128;
    const int tid = threadIdx.x, lane = tid & 31, warp = tid >> 5;
    const int wm = warp & 3, wn = warp >> 2;
    const int row = tid >> 1, c0off = (tid & 1)*16;
    const float* ag = Gact + ((size_t)e*Tt + m0 + row)*IEXP + c0off;
    const float* bg = B + (size_t)(n0+row)*IEXP + c0off;

    float acc[2][8][4];
    #pragma unroll
    for (int i=0;i<2;i++) for (int j=0;j<8;j++) for (int c=0;c<4;c++) acc[i][j][c]=0.f;

    tf32_db(S, ag, bg, row, c0off, IEXP, lane, wm, wn, acc);

    const int* lst = g_elist + e*Tt;
    const int g = lane >> 2, t = lane & 3;
    #pragma unroll
    for (int mt = 0; mt < 2; mt++) {
        int r0 = m0 + wm*32 + mt*16 + g;
        #pragma unroll
        for (int nt = 0; nt < 8; nt++) {
            int gn = n0 + wn*64 + nt*8 + t*2;
            if (r0 < count) {
                float2 v; v.x = acc[mt][nt][0]; v.y = acc[mt][nt][1];
                *(float2*)(ydown + (size_t)lst[r0]*Hh + gn) = v;
            }
            if (r0+8 < count) {
                float2 v; v.x = acc[mt][nt][2]; v.y = acc[mt][nt][3];
                *(float2*)(ydown + (size_t)lst[r0+8]*Hh + gn) = v;
            }
        }
    }
}

// ---------------- rmsnorm ----------------
__global__ __launch_bounds__(256) void rmsnorm_kernel(
    const float* __restrict__ x, const float* __restrict__ w, float* __restrict__ y)
{
    int t = blockIdx.x;
    const float* xr = x + (size_t)t*Hh;
    float s = 0.f;
    for (int i = threadIdx.x; i < Hh; i += 256) { float v = xr[i]; s += v*v; }
    #pragma unroll
    for (int o = 16; o > 0; o >>= 1) s += __shfl_xor_sync(0xffffffffu, s, o);
    __shared__ float red[8];
    if ((threadIdx.x & 31) == 0) red[threadIdx.x >> 5] = s;
    __syncthreads();
    float tot = 0.f;
    #pragma unroll
    for (int wv = 0; wv < 8; wv++) tot += red[wv];
    float inv = rsqrtf(tot * (1.0f/(float)Hh) + EPSf);
    float* yr = y + (size_t)t*Hh;
    for (int i = threadIdx.x; i < Hh; i += 256) yr[i] = w[i]*xr[i]*inv;
}

// ---------------- RoPE ----------------
__global__ void rope_kernel(float* __restrict__ a, int nheads,
                            const int* __restrict__ pos_ids,
                            const float* __restrict__ cosb,
                            const float* __restrict__ sinb)
{
    int idx = blockIdx.x*256 + threadIdx.x;
    int total = Tt * nheads * 64;
    if (idx >= total) return;
    int dd = idx & 63;
    int hh = (idx >> 6) % nheads;
    int t  = idx / (64*nheads);
    int pos = pos_ids[t] & 4095;
    float c1 = cosb[pos*Dd + dd],      s1 = sinb[pos*Dd + dd];
    float c2 = cosb[pos*Dd + dd + 64], s2 = sinb[pos*Dd + dd + 64];
    float* base = a + (size_t)t*(nheads*Dd) + hh*Dd;
    float x1 = base[dd], x2 = base[dd+64];
    base[dd]     = x1*c1 - x2*s1;
    base[dd+64]  = x2*c2 + x1*s2;
}

// ---------------- flash attention, 32x32 tiles, static smem ----------------
__global__ __launch_bounds__(256) void attn_kernel(
    const float* __restrict__ Q, const float* __restrict__ Kg,
    const float* __restrict__ Vg, float* __restrict__ O)
{
    __shared__ float Qt[128][33];
    __shared__ float KV[128*33];
    __shared__ float Pt[32][33];
    int qt = blockIdx.x, h = blockIdx.y, b = blockIdx.z;
    int kvh = h / (NHq/NKVh);
    int tid = threadIdx.x;
    int tx = tid & 15, ty = tid >> 4;
    int tq0 = b*Ss + qt*32;

    #pragma unroll
    for (int i = 0; i < 4; i++) {
        int v = tid + i*256;
        int r = v >> 5;
        int dq = (v & 31) << 2;
        float4 qv = *(const float4*)(Q + (size_t)(tq0+r)*Hh + h*Dd + dq);
        Qt[dq+0][r] = qv.x * SCALEf;
        Qt[dq+1][r] = qv.y * SCALEf;
        Qt[dq+2][r] = qv.z * SCALEf;
        Qt[dq+3][r] = qv.w * SCALEf;
    }

    float m_i[2], l_i[2], acc[2][8];
    #pragma unroll
    for (int i = 0; i < 2; i++) {
        m_i[i] = -1e30f; l_i[i] = 0.f;
        #pragma unroll
        for (int j = 0; j < 8; j++) acc[i][j] = 0.f;
    }

    for (int kt = 0; kt <= qt; kt++) {
        int tk0 = b*Ss + kt*32;
        __syncthreads();
        #pragma unroll
        for (int i = 0; i < 4; i++) {
            int v = tid + i*256;
            int r = v >> 5;
            int dq = (v & 31) << 2;
            float4 kv = *(const float4*)(Kg + (size_t)(tk0+r)*(NKVh*Dd) + kvh*Dd + dq);
            KV[(dq+0)*33 + r] = kv.x; KV[(dq+1)*33 + r] = kv.y;
            KV[(dq+2)*33 + r] = kv.z; KV[(dq+3)*33 + r] = kv.w;
        }
        __syncthreads();

        float s[2][2];
        s[0][0]=s[0][1]=s[1][0]=s[1][1]=0.f;
        for (int d = 0; d < 128; d++) {
            float a0 = Qt[d][ty*2+0], a1 = Qt[d][ty*2+1];
            float b0 = KV[d*33 + tx*2+0], b1 = KV[d*33 + tx*2+1];
            s[0][0] += a0*b0; s[0][1] += a0*b1;
            s[1][0] += a1*b0; s[1][1] += a1*b1;
        }
        if (kt == qt) {
            #pragma unroll
            for (int i = 0; i < 2; i++)
                #pragma unroll
                for (int j = 0; j < 2; j++)
                    if (tx*2 + j > ty*2 + i) s[i][j] = -1e30f;
        }
        #pragma unroll
        for (int i = 0; i < 2; i++) {
            float mx = fmaxf(s[i][0], s[i][1]);
            #pragma unroll
            for (int o = 1; o < 16; o <<= 1) mx = fmaxf(mx, __shfl_xor_sync(0xffffffffu, mx, o));
            float mn = fmaxf(m_i[i], mx);
            float p0 = __expf(s[i][0] - mn);
            float p1 = __expf(s[i][1] - mn);
            float psum = p0 + p1;
            #pragma unroll
            for (int o = 1; o < 16; o <<= 1) psum += __shfl_xor_sync(0xffffffffu, psum, o);
            float f = __expf(m_i[i] - mn);
            l_i[i] = l_i[i]*f + psum;
            m_i[i] = mn;
            #pragma unroll
            for (int j = 0; j < 8; j++) acc[i][j] *= f;
            Pt[tx*2+0][ty*2+i] = p0;
            Pt[tx*2+1][ty*2+i] = p1;
        }
        __syncthreads();
        #pragma unroll
        for (int i = 0; i < 4; i++) {
            int v = tid + i*256;
            int r = v >> 5;
            int dq = (v & 31) << 2;
            float4 vv = *(const float4*)(Vg + (size_t)(tk0+r)*(NKVh*Dd) + kvh*Dd + dq);
            *(float4*)(KV + r*128 + dq) = vv;
        }
        __syncthreads();
        for (int k = 0; k < 32; k++) {
            float a0 = Pt[k][ty*2+0], a1 = Pt[k][ty*2+1];
            float bb[8];
            *(float4*)&bb[0] = *(const float4*)(KV + k*128 + tx*8);
            *(float4*)&bb[4] = *(const float4*)(KV + k*128 + tx*8 + 4);
            #pragma unroll
            for (int j = 0; j < 8; j++) {
                acc[0][j] += a0*bb[j];
                acc[1][j] += a1*bb[j];
            }
        }
    }
    #pragma unroll
    for (int i = 0; i < 2; i++) {
        float inv = 1.0f / l_i[i];
        int t = tq0 + ty*2 + i;
        float4 o1, o2;
        o1.x = acc[i][0]*inv; o1.y = acc[i][1]*inv; o1.z = acc[i][2]*inv; o1.w = acc[i][3]*inv;
        o2.x = acc[i][4]*inv; o2.y = acc[i][5]*inv; o2.z = acc[i][6]*inv; o2.w = acc[i][7]*inv;
        *(float4*)(O + (size_t)t*Hh + h*Dd + tx*8)     = o1;
        *(float4*)(O + (size_t)t*Hh + h*Dd + tx*8 + 4) = o2;
    }
}

// ---------------- router ----------------
__global__ void zero_counts() { if (threadIdx.x < Ee) g_ecount[threadIdx.x] = 0; }

__global__ __launch_bounds__(256) void router_kernel(
    const float* __restrict__ x, const float* __restrict__ rw)
{
    int t = blockIdx.x;
    const float* xr = x + (size_t)t*Hh;
    float acc[Ee];
    #pragma unroll
    for (int e = 0; e < Ee; e++) acc[e] = 0.f;
    for (int hh = threadIdx.x; hh < Hh; hh += 256) {
        float xv = xr[hh];
        #pragma unroll
        for (int e = 0; e < Ee; e++) acc[e] += xv * rw[e*Hh + hh];
    }
    #pragma unroll
    for (int e = 0; e < Ee; e++)
        #pragma unroll
        for (int o = 16; o > 0; o >>= 1) acc[e] += __shfl_xor_sync(0xffffffffu, acc[e], o);
    __shared__ float red[8][Ee];
    int warp = threadIdx.x >> 5, lane = threadIdx.x & 31;
    if (lane == 0)
        for (int e = 0; e < Ee; e++) red[warp][e] = acc[e];
    __syncthreads();
    if (threadIdx.x == 0) {
        float l[Ee];
        for (int e = 0; e < Ee; e++) {
            float ssum = 0.f;
            for (int w = 0; w < 8; w++) ssum += red[w][e];
            l[e] = ssum;
        }
        int i1 = 0;
        for (int e = 1; e < Ee; e++) if (l[e] > l[i1]) i1 = e;
        int i2 = -1;
        for (int e = 0; e < Ee; e++) if (e != i1 && (i2 < 0 || l[e] > l[i2])) i2 = e;
        float w1 = 1.f / (1.f + __expf(l[i2] - l[i1]));
        g_rwflat[2*t]   = w1;
        g_rwflat[2*t+1] = 1.f - w1;
        int p1 = atomicAdd(&g_ecount[i1], 1); g_elist[i1*Tt + p1] = 2*t;
        int p2 = atomicAdd(&g_ecount[i2], 1); g_elist[i2*Tt + p2] = 2*t + 1;
    }
}

// ---------------- elementwise ----------------
__global__ void swiglu_moe_kernel(float* __restrict__ gb, const float* __restrict__ ub)
{
    int idx = blockIdx.x*256 + threadIdx.x;
    int e = idx >> 21;
    int r = (idx >> 9) & 4095;
    if (r >= g_ecount[e]) return;
    float g = gb[idx], u = ub[idx];
    gb[idx] = g * u / (1.f + __expf(-g));
}

__global__ void swiglu_shared_kernel(const float* __restrict__ shg, float* __restrict__ sha)
{
    int idx = blockIdx.x*256 + threadIdx.x;
    int t = idx >> 10;
    int i = idx & 1023;
    float a = shg[(size_t)t*2*ISH + i];
    float b = shg[(size_t)t*2*ISH + ISH + i];
    sha[idx] = a * b / (1.f + __expf(-a));
}

__global__ void combine_kernel(const float* __restrict__ hid,
                               const float* __restrict__ yd,
                               const float* __restrict__ shr,
                               float* __restrict__ out)
{
    int idx = blockIdx.x*256 + threadIdx.x;
    int t = idx / Hh;
    int c = idx - t*Hh;
    float mo = g_rwflat[2*t]   * yd[(size_t)(2*t)*Hh + c]
             + g_rwflat[2*t+1] * yd[(size_t)(2*t+1)*Hh + c];
    out[idx] = hid[idx] + RESMf * (mo + shr[idx]);
}

// ---------------- launch ----------------
extern "C" void kernel_launch(void* const* d_in, const int* in_sizes, int n_in,
                              void* d_out, int out_size)
{
    const float* hidden    = (const float*)d_in[0];
    const int*   pos       = (const int*)  d_in[1];
    const float* cosb      = (const float*)d_in[2];
    const float* sinb      = (const float*)d_in[3];
    const float* ln1       = (const float*)d_in[4];
    const float* ln2       = (const float*)d_in[5];
    const float* wq        = (const float*)d_in[6];
    const float* wk        = (const float*)d_in[7];
    const float* wv        = (const float*)d_in[8];
    const float* wo        = (const float*)d_in[9];
    const float* router_w  = (const float*)d_in[10];
    const float* w_gate    = (const float*)d_in[11];
    const float* w_up      = (const float*)d_in[12];
    const float* w_down    = (const float*)d_in[13];
    const float* shared_in = (const float*)d_in[14];
    const float* shared_ot = (const float*)d_in[15];
    float* out = (float*)d_out;

    float *p_xnorm, *p_q, *p_k, *p_v, *p_attn, *p_hidden, *p_x2;
    float *p_shg, *p_shh, *p_shared, *p_gbuf, *p_ubuf, *p_ydown;
    cudaGetSymbolAddress((void**)&p_xnorm,  g_xnorm);
    cudaGetSymbolAddress((void**)&p_q,      g_q);
    cudaGetSymbolAddress((void**)&p_k,      g_k);
    cudaGetSymbolAddress((void**)&p_v,      g_v);
    cudaGetSymbolAddress((void**)&p_attn,   g_attn);
    cudaGetSymbolAddress((void**)&p_hidden, g_hidden);
    cudaGetSymbolAddress((void**)&p_x2,     g_x2);
    cudaGetSymbolAddress((void**)&p_shg,    g_shgate);
    cudaGetSymbolAddress((void**)&p_shh,    g_shh);
    cudaGetSymbolAddress((void**)&p_shared, g_shared);
    cudaGetSymbolAddress((void**)&p_gbuf,   g_gbuf);
    cudaGetSymbolAddress((void**)&p_ubuf,   g_ubuf);
    cudaGetSymbolAddress((void**)&p_ydown,  g_ydown);

    cudaFuncSetAttribute(tc_gemm,     cudaFuncAttributeMaxDynamicSharedMemorySize, SMEM_BYTES);
    cudaFuncSetAttribute(tc_qkv,      cudaFuncAttributeMaxDynamicSharedMemorySize, SMEM_BYTES);
    cudaFuncSetAttribute(tc_moe_gu,   cudaFuncAttributeMaxDynamicSharedMemorySize, SMEM_BYTES);
    cudaFuncSetAttribute(tc_moe_down, cudaFuncAttributeMaxDynamicSharedMemorySize, SMEM_BYTES);

    // ---- attention block ----
    rmsnorm_kernel<<<Tt, 256>>>(hidden, ln1, p_xnorm);
    tc_qkv<<<dim3(20,32), 256, SMEM_BYTES>>>(p_xnorm, wq, wk, wv, p_q, p_k, p_v);
    rope_kernel<<<(Tt*NHq*64 + 255)/256, 256>>>(p_q, NHq, pos, cosb, sinb);
    rope_kernel<<<(Tt*NKVh*64 + 255)/256, 256>>>(p_k, NKVh, pos, cosb, sinb);
    attn_kernel<<<dim3(64, NHq, Bb), 256>>>(p_q, p_k, p_v, p_attn);
    tc_gemm<<<dim3(12,32), 256, SMEM_BYTES>>>(p_attn, Hh, wo, Hh, p_hidden, Hh, Hh, RESMf, hidden);

    // ---- MoE + shared MLP block ----
    rmsnorm_kernel<<<Tt, 256>>>(p_hidden, ln2, p_x2);
    zero_counts<<<1, 32>>>();
    router_kernel<<<Tt, 256>>>(p_x2, router_w);
    tc_gemm<<<dim3(16,32), 256, SMEM_BYTES>>>(p_x2, Hh, shared_in, Hh, p_shg, 2*ISH, Hh, 1.f, nullptr);
    tc_moe_gu<<<dim3(8,32,Ee), 256, SMEM_BYTES>>>(p_x2, w_gate, w_up, p_gbuf, p_ubuf);
    swiglu_moe_kernel<<<(Ee*Tt*IEXP)/256, 256>>>(p_gbuf, p_ubuf);
    tc_moe_down<<<dim3(12,32,Ee), 256, SMEM_BYTES>>>(p_gbuf, w_down, p_ydown);
    swiglu_shared_kernel<<<(Tt*ISH)/256, 256>>>(p_shg, p_shh);
    tc_gemm<<<dim3(12,32), 256, SMEM_BYTES>>>(p_shh, ISH, shared_ot, ISH, p_shared, Hh, ISH, 1.f, nullptr);
    combine_kernel<<<(Tt*Hh)/256, 256>>>(p_hidden, p_ydown, p_shared, out);
}

// round 13
// speedup vs baseline: 3.5664x; 1.9279x over previous
#include <cuda_runtime.h>
#include <cstdint>

// ---------------- problem constants ----------------
#define Bb 2
#define Ss 2048
#define Hh 1536
#define NHq 12
#define NKVh 4
#define Dd 128
#define Tt (Bb*Ss)          // 4096
#define Ee 8
#define IEXP 512
#define ISH 1024
#define SCALEf 0.0078125f
#define RESMf 0.22f
#define EPSf 1e-6f

// ---------------- scratch ----------------
__device__ float g_xnorm [Tt*Hh];
__device__ float g_q     [Tt*Hh];
__device__ float g_k     [Tt*NKVh*Dd];
__device__ float g_v     [Tt*NKVh*Dd];
__device__ float g_attn  [Tt*Hh];
__device__ float g_hidden[Tt*Hh];
__device__ float g_x2    [Tt*Hh];
__device__ float g_shgate[Tt*2*ISH];
__device__ float g_shh   [Tt*ISH];
__device__ float g_shared[Tt*Hh];
__device__ float g_gbuf  [Ee*Tt*IEXP];
__device__ float g_ubuf  [Ee*Tt*IEXP];
__device__ float g_ydown [Tt*2*Hh];
__device__ int   g_elist [Ee*Tt];
__device__ int   g_ecount[Ee];
__device__ float g_rwflat[Tt*2];

// ---------------- tf32 helpers ----------------
__device__ __forceinline__ unsigned f2tf(float x)
{
    unsigned u;
    asm("cvt.rna.tf32.f32 %0, %1;" : "=r"(u) : "f"(x));
    return u;
}

#define MMA_TF32(acc, a0,a1,a2,a3, b0,b1) \
    asm volatile( \
        "mma.sync.aligned.m16n8k8.row.col.f32.tf32.tf32.f32 " \
        "{%0,%1,%2,%3}, {%4,%5,%6,%7}, {%8,%9}, {%0,%1,%2,%3};" \
        : "+f"((acc)[0]), "+f"((acc)[1]), "+f"((acc)[2]), "+f"((acc)[3]) \
        : "r"(a0), "r"(a1), "r"(a2), "r"(a3), "r"(b0), "r"(b1))

struct SmemT {
    float As[2][128][36];
    float Bs[2][128][36];
};
#define SMEM_BYTES ((int)sizeof(SmemT))   // 73728

// 16 mma per warp per k8; warp tile 32x64
__device__ __forceinline__ void mma_compute(
    const float (&A)[128][36], const float (&B)[128][36],
    int lane, int wm, int wn, float (&acc)[2][8][4])
{
    const int g = lane >> 2, t = lane & 3;
    #pragma unroll
    for (int kk = 0; kk < 4; kk++) {
        const int kb = kk*8;
        unsigned af[2][4];
        #pragma unroll
        for (int mt = 0; mt < 2; mt++) {
            int ar = wm*32 + mt*16 + g;
            af[mt][0] = __float_as_uint(A[ar  ][kb+t  ]);
            af[mt][1] = __float_as_uint(A[ar+8][kb+t  ]);
            af[mt][2] = __float_as_uint(A[ar  ][kb+t+4]);
            af[mt][3] = __float_as_uint(A[ar+8][kb+t+4]);
        }
        #pragma unroll
        for (int nt = 0; nt < 8; nt++) {
            int br = wn*64 + nt*8 + g;
            unsigned b0 = __float_as_uint(B[br][kb+t  ]);
            unsigned b1 = __float_as_uint(B[br][kb+t+4]);
            #pragma unroll
            for (int mt = 0; mt < 2; mt++)
                MMA_TF32(acc[mt][nt], af[mt][0],af[mt][1],af[mt][2],af[mt][3], b0,b1);
        }
    }
}

__device__ __forceinline__ void tf32_db(
    SmemT& S,
    const float* ag, const float* bg,
    int row, int c0off, int K,
    int lane, int wm, int wn,
    float (&acc)[2][8][4])
{
    #pragma unroll
    for (int i = 0; i < 4; i++) {
        float4 a = ag ? *(const float4*)(ag + i*4) : make_float4(0.f,0.f,0.f,0.f);
        float4 b = *(const float4*)(bg + i*4);
        S.As[0][row][c0off+i*4+0] = __uint_as_float(f2tf(a.x));
        S.As[0][row][c0off+i*4+1] = __uint_as_float(f2tf(a.y));
        S.As[0][row][c0off+i*4+2] = __uint_as_float(f2tf(a.z));
        S.As[0][row][c0off+i*4+3] = __uint_as_float(f2tf(a.w));
        S.Bs[0][row][c0off+i*4+0] = __uint_as_float(f2tf(b.x));
        S.Bs[0][row][c0off+i*4+1] = __uint_as_float(f2tf(b.y));
        S.Bs[0][row][c0off+i*4+2] = __uint_as_float(f2tf(b.z));
        S.Bs[0][row][c0off+i*4+3] = __uint_as_float(f2tf(b.w));
    }
    __syncthreads();

    int cur = 0;
    for (int k0 = 32; k0 < K; k0 += 32) {
        float4 an[4], bn[4];
        #pragma unroll
        for (int i = 0; i < 4; i++) {
            an[i] = ag ? *(const float4*)(ag + k0 + i*4) : make_float4(0.f,0.f,0.f,0.f);
            bn[i] = *(const float4*)(bg + k0 + i*4);
        }
        mma_compute(S.As[cur], S.Bs[cur], lane, wm, wn, acc);
        int nxt = cur ^ 1;
        #pragma unroll
        for (int i = 0; i < 4; i++) {
            S.As[nxt][row][c0off+i*4+0] = __uint_as_float(f2tf(an[i].x));
            S.As[nxt][row][c0off+i*4+1] = __uint_as_float(f2tf(an[i].y));
            S.As[nxt][row][c0off+i*4+2] = __uint_as_float(f2tf(an[i].z));
            S.As[nxt][row][c0off+i*4+3] = __uint_as_float(f2tf(an[i].w));
            S.Bs[nxt][row][c0off+i*4+0] = __uint_as_float(f2tf(bn[i].x));
            S.Bs[nxt][row][c0off+i*4+1] = __uint_as_float(f2tf(bn[i].y));
            S.Bs[nxt][row][c0off+i*4+2] = __uint_as_float(f2tf(bn[i].z));
            S.Bs[nxt][row][c0off+i*4+3] = __uint_as_float(f2tf(bn[i].w));
        }
        __syncthreads();
        cur = nxt;
    }
    mma_compute(S.As[cur], S.Bs[cur], lane, wm, wn, acc);
}

// ---------------- generic TN GEMM (tf32) ----------------
__global__ void __launch_bounds__(256, 2) tc_gemm(
    const float* __restrict__ A, int lda,
    const float* __restrict__ B, int ldb,
    float* __restrict__ C, int ldc,
    int K, float alpha, const float* __restrict__ res)
{
    extern __shared__ char smemraw[];
    SmemT& S = *reinterpret_cast<SmemT*>(smemraw);
    const int tid = threadIdx.x, lane = tid & 31, warp = tid >> 5;
    const int wm = warp & 3, wn = warp >> 2;
    const int m0 = blockIdx.y*128, n0 = blockIdx.x*128;
    const int row = tid >> 1, c0off = (tid & 1)*16;
    const float* ag = A + (size_t)(m0+row)*lda + c0off;
    const float* bg = B + (size_t)(n0+row)*ldb + c0off;

    float acc[2][8][4];
    #pragma unroll
    for (int i=0;i<2;i++) for (int j=0;j<8;j++) for (int c=0;c<4;c++) acc[i][j][c]=0.f;

    tf32_db(S, ag, bg, row, c0off, K, lane, wm, wn, acc);

    const int g = lane >> 2, t = lane & 3;
    #pragma unroll
    for (int mt = 0; mt < 2; mt++) {
        int gm = m0 + wm*32 + mt*16 + g;
        #pragma unroll
        for (int nt = 0; nt < 8; nt++) {
            int gn = n0 + wn*64 + nt*8 + t*2;
            float2 v0, v1;
            v0.x = alpha*acc[mt][nt][0]; v0.y = alpha*acc[mt][nt][1];
            v1.x = alpha*acc[mt][nt][2]; v1.y = alpha*acc[mt][nt][3];
            if (res) {
                const float* r0 = res + (size_t)gm*ldc + gn;
                const float* r1 = res + (size_t)(gm+8)*ldc + gn;
                v0.x += r0[0]; v0.y += r0[1];
                v1.x += r1[0]; v1.y += r1[1];
            }
            *(float2*)(C + (size_t)gm*ldc + gn)     = v0;
            *(float2*)(C + (size_t)(gm+8)*ldc + gn) = v1;
        }
    }
}

// ---------------- fused QKV (tf32) ----------------
__global__ void __launch_bounds__(256, 2) tc_qkv(
    const float* __restrict__ A,
    const float* __restrict__ wq, const float* __restrict__ wk, const float* __restrict__ wv,
    float* __restrict__ q, float* __restrict__ k, float* __restrict__ v)
{
    extern __shared__ char smemraw[];
    SmemT& S = *reinterpret_cast<SmemT*>(smemraw);
    const int bx = blockIdx.x;
    const float* B; float* C; int ldc, n0;
    if (bx < 12)      { B = wq; C = q; ldc = Hh;      n0 = bx*128; }
    else if (bx < 16) { B = wk; C = k; ldc = NKVh*Dd; n0 = (bx-12)*128; }
    else              { B = wv; C = v; ldc = NKVh*Dd; n0 = (bx-16)*128; }

    const int tid = threadIdx.x, lane = tid & 31, warp = tid >> 5;
    const int wm = warp & 3, wn = warp >> 2;
    const int m0 = blockIdx.y*128;
    const int row = tid >> 1, c0off = (tid & 1)*16;
    const float* ag = A + (size_t)(m0+row)*Hh + c0off;
    const float* bg = B + (size_t)(n0+row)*Hh + c0off;

    float acc[2][8][4];
    #pragma unroll
    for (int i=0;i<2;i++) for (int j=0;j<8;j++) for (int c=0;c<4;c++) acc[i][j][c]=0.f;

    tf32_db(S, ag, bg, row, c0off, Hh, lane, wm, wn, acc);

    const int g = lane >> 2, t = lane & 3;
    #pragma unroll
    for (int mt = 0; mt < 2; mt++) {
        int gm = m0 + wm*32 + mt*16 + g;
        #pragma unroll
        for (int nt = 0; nt < 8; nt++) {
            int gn = n0 + wn*64 + nt*8 + t*2;
            float2 v0, v1;
            v0.x = acc[mt][nt][0]; v0.y = acc[mt][nt][1];
            v1.x = acc[mt][nt][2]; v1.y = acc[mt][nt][3];
            *(float2*)(C + (size_t)gm*ldc + gn)     = v0;
            *(float2*)(C + (size_t)(gm+8)*ldc + gn) = v1;
        }
    }
}

// ---------------- MoE gate+up (tf32) ----------------
__global__ void __launch_bounds__(256, 2) tc_moe_gu(
    const float* __restrict__ X,
    const float* __restrict__ w_gate, const float* __restrict__ w_up,
    float* __restrict__ gbuf, float* __restrict__ ubuf)
{
    const int e = blockIdx.z;
    const int count = g_ecount[e];
    const int m0 = blockIdx.y*128;
    if (m0 >= count) return;
    extern __shared__ char smemraw[];
    SmemT& S = *reinterpret_cast<SmemT*>(smemraw);
    __shared__ int rowmap[128];

    const int bx = blockIdx.x;
    const float* B = (bx < 4 ? w_gate : w_up) + (size_t)e*IEXP*Hh;
    float* C = (bx < 4 ? gbuf : ubuf);
    const int n0 = (bx & 3)*128;

    const int tid = threadIdx.x, lane = tid & 31, warp = tid >> 5;
    const int wm = warp & 3, wn = warp >> 2;
    const int row = tid >> 1, c0off = (tid & 1)*16;
    if (tid < 128) {
        int r = m0 + tid;
        rowmap[tid] = (r < count) ? (g_elist[e*Tt + r] >> 1) : -1;
    }
    __syncthreads();
    int src = rowmap[row];
    const float* ag = (src >= 0) ? X + (size_t)src*Hh + c0off : nullptr;
    const float* bg = B + (size_t)(n0+row)*Hh + c0off;

    float acc[2][8][4];
    #pragma unroll
    for (int i=0;i<2;i++) for (int j=0;j<8;j++) for (int c=0;c<4;c++) acc[i][j][c]=0.f;

    tf32_db(S, ag, bg, row, c0off, Hh, lane, wm, wn, acc);

    const int g = lane >> 2, t = lane & 3;
    #pragma unroll
    for (int mt = 0; mt < 2; mt++) {
        int r0 = m0 + wm*32 + mt*16 + g;
        #pragma unroll
        for (int nt = 0; nt < 8; nt++) {
            int gn = n0 + wn*64 + nt*8 + t*2;
            if (r0 < count) {
                float2 v; v.x = acc[mt][nt][0]; v.y = acc[mt][nt][1];
                *(float2*)(C + ((size_t)e*Tt + r0)*IEXP + gn) = v;
            }
            if (r0+8 < count) {
                float2 v; v.x = acc[mt][nt][2]; v.y = acc[mt][nt][3];
                *(float2*)(C + ((size_t)e*Tt + r0+8)*IEXP + gn) = v;
            }
        }
    }
}

// ---------------- MoE down (tf32) ----------------
__global__ void __launch_bounds__(256, 2) tc_moe_down(
    const float* __restrict__ Gact,
    const float* __restrict__ w_down,
    float* __restrict__ ydown)
{
    const int e = blockIdx.z;
    const int count = g_ecount[e];
    const int m0 = blockIdx.y*128;
    if (m0 >= count) return;
    extern __shared__ char smemraw[];
    SmemT& S = *reinterpret_cast<SmemT*>(smemraw);

    const float* B = w_down + (size_t)e*Hh*IEXP;
    const int n0 = blockIdx.x*128;
    const int tid = threadIdx.x, lane = tid & 31, warp = tid >> 5;
    const int wm = warp & 3, wn = warp >> 2;
    const int row = tid >> 1, c0off = (tid & 1)*16;
    const float* ag = Gact + ((size_t)e*Tt + m0 + row)*IEXP + c0off;
    const float* bg = B + (size_t)(n0+row)*IEXP + c0off;

    float acc[2][8][4];
    #pragma unroll
    for (int i=0;i<2;i++) for (int j=0;j<8;j++) for (int c=0;c<4;c++) acc[i][j][c]=0.f;

    tf32_db(S, ag, bg, row, c0off, IEXP, lane, wm, wn, acc);

    const int* lst = g_elist + e*Tt;
    const int g = lane >> 2, t = lane & 3;
    #pragma unroll
    for (int mt = 0; mt < 2; mt++) {
        int r0 = m0 + wm*32 + mt*16 + g;
        #pragma unroll
        for (int nt = 0; nt < 8; nt++) {
            int gn = n0 + wn*64 + nt*8 + t*2;
            if (r0 < count) {
                float2 v; v.x = acc[mt][nt][0]; v.y = acc[mt][nt][1];
                *(float2*)(ydown + (size_t)lst[r0]*Hh + gn) = v;
            }
            if (r0+8 < count) {
                float2 v; v.x = acc[mt][nt][2]; v.y = acc[mt][nt][3];
                *(float2*)(ydown + (size_t)lst[r0+8]*Hh + gn) = v;
            }
        }
    }
}

// ---------------- tf32 flash attention: 64q x 64kv tiles, 4 warps ----------------
struct AttnSmem {
    float Qs[64][132];
    float KV[64][132];   // K tile, then V tile
    float Ps[64][68];
};
#define ATTN_SMEM ((int)sizeof(AttnSmem))  // 84992

__global__ void __launch_bounds__(128, 2) tc_attn(
    const float* __restrict__ Q, const float* __restrict__ Kg,
    const float* __restrict__ Vg, float* __restrict__ O)
{
    extern __shared__ char sraw[];
    AttnSmem& S = *reinterpret_cast<AttnSmem*>(sraw);
    const int qt = blockIdx.x, h = blockIdx.y, b = blockIdx.z;
    const int kvh = h / (NHq/NKVh);
    const int tid = threadIdx.x, lane = tid & 31, warp = tid >> 5;
    const int g = lane >> 2, t = lane & 3;
    const int tq0 = b*Ss + qt*64;
    const int rA = warp*16 + g;          // this thread's A rows: rA, rA+8

    // load Q tile (scaled, tf32)
    #pragma unroll
    for (int i = 0; i < 16; i++) {
        int v = tid + i*128;
        int r = v >> 5, dq = (v & 31) << 2;
        float4 qv = *(const float4*)(Q + (size_t)(tq0+r)*Hh + h*Dd + dq);
        S.Qs[r][dq+0] = __uint_as_float(f2tf(qv.x * SCALEf));
        S.Qs[r][dq+1] = __uint_as_float(f2tf(qv.y * SCALEf));
        S.Qs[r][dq+2] = __uint_as_float(f2tf(qv.z * SCALEf));
        S.Qs[r][dq+3] = __uint_as_float(f2tf(qv.w * SCALEf));
    }

    float o[16][4];
    #pragma unroll
    for (int i = 0; i < 16; i++)
        #pragma unroll
        for (int c = 0; c < 4; c++) o[i][c] = 0.f;
    float m0v = -1e30f, m1v = -1e30f, l0 = 0.f, l1 = 0.f;

    for (int kt = 0; kt <= qt; kt++) {
        const int tk0 = b*Ss + kt*64;
        __syncthreads();  // KV overwrite safe (prev PV done); 1st iter: Qs ready
        #pragma unroll
        for (int i = 0; i < 16; i++) {
            int v = tid + i*128;
            int r = v >> 5, dq = (v & 31) << 2;
            float4 kv = *(const float4*)(Kg + (size_t)(tk0+r)*(NKVh*Dd) + kvh*Dd + dq);
            S.KV[r][dq+0] = __uint_as_float(f2tf(kv.x));
            S.KV[r][dq+1] = __uint_as_float(f2tf(kv.y));
            S.KV[r][dq+2] = __uint_as_float(f2tf(kv.z));
            S.KV[r][dq+3] = __uint_as_float(f2tf(kv.w));
        }
        __syncthreads();

        // S = Q K^T  (warp: 16 rows x 64 cols)
        float s[8][4];
        #pragma unroll
        for (int nt = 0; nt < 8; nt++)
            #pragma unroll
            for (int c = 0; c < 4; c++) s[nt][c] = 0.f;
        #pragma unroll
        for (int kk = 0; kk < 16; kk++) {
            const int kb = kk*8;
            unsigned a0 = __float_as_uint(S.Qs[rA  ][kb+t  ]);
            unsigned a1 = __float_as_uint(S.Qs[rA+8][kb+t  ]);
            unsigned a2 = __float_as_uint(S.Qs[rA  ][kb+t+4]);
            unsigned a3 = __float_as_uint(S.Qs[rA+8][kb+t+4]);
            #pragma unroll
            for (int nt = 0; nt < 8; nt++) {
                unsigned b0 = __float_as_uint(S.KV[nt*8+g][kb+t  ]);
                unsigned b1 = __float_as_uint(S.KV[nt*8+g][kb+t+4]);
                MMA_TF32(s[nt], a0,a1,a2,a3, b0,b1);
            }
        }
        if (kt == qt) {
            #pragma unroll
            for (int nt = 0; nt < 8; nt++)
                #pragma unroll
                for (int j = 0; j < 2; j++) {
                    int col = nt*8 + t*2 + j;
                    if (col > rA)   s[nt][j]   = -1e30f;
                    if (col > rA+8) s[nt][2+j] = -1e30f;
                }
        }
        // online softmax per row (rows rA and rA+8)
        float mx0 = -1e30f, mx1 = -1e30f;
        #pragma unroll
        for (int nt = 0; nt < 8; nt++) {
            mx0 = fmaxf(mx0, fmaxf(s[nt][0], s[nt][1]));
            mx1 = fmaxf(mx1, fmaxf(s[nt][2], s[nt][3]));
        }
        mx0 = fmaxf(mx0, __shfl_xor_sync(0xffffffffu, mx0, 1));
        mx0 = fmaxf(mx0, __shfl_xor_sync(0xffffffffu, mx0, 2));
        mx1 = fmaxf(mx1, __shfl_xor_sync(0xffffffffu, mx1, 1));
        mx1 = fmaxf(mx1, __shfl_xor_sync(0xffffffffu, mx1, 2));
        float mn0 = fmaxf(m0v, mx0), mn1 = fmaxf(m1v, mx1);
        float sc0 = __expf(m0v - mn0), sc1 = __expf(m1v - mn1);
        float sum0 = 0.f, sum1 = 0.f;
        #pragma unroll
        for (int nt = 0; nt < 8; nt++) {
            float p0 = __expf(s[nt][0] - mn0);
            float p1 = __expf(s[nt][1] - mn0);
            float p2 = __expf(s[nt][2] - mn1);
            float p3 = __expf(s[nt][3] - mn1);
            sum0 += p0 + p1; sum1 += p2 + p3;
            int c = nt*8 + t*2;
            S.Ps[rA  ][c]   = __uint_as_float(f2tf(p0));
            S.Ps[rA  ][c+1] = __uint_as_float(f2tf(p1));
            S.Ps[rA+8][c]   = __uint_as_float(f2tf(p2));
            S.Ps[rA+8][c+1] = __uint_as_float(f2tf(p3));
        }
        sum0 += __shfl_xor_sync(0xffffffffu, sum0, 1);
        sum0 += __shfl_xor_sync(0xffffffffu, sum0, 2);
        sum1 += __shfl_xor_sync(0xffffffffu, sum1, 1);
        sum1 += __shfl_xor_sync(0xffffffffu, sum1, 2);
        l0 = l0*sc0 + sum0; l1 = l1*sc1 + sum1;
        m0v = mn0; m1v = mn1;
        #pragma unroll
        for (int nt = 0; nt < 16; nt++) {
            o[nt][0] *= sc0; o[nt][1] *= sc0;
            o[nt][2] *= sc1; o[nt][3] *= sc1;
        }
        __syncthreads();  // Ps written; K reads done
        // load V tile (row-major [kv][d], tf32)
        #pragma unroll
        for (int i = 0; i < 16; i++) {
            int v = tid + i*128;
            int r = v >> 5, dq = (v & 31) << 2;
            float4 vv = *(const float4*)(Vg + (size_t)(tk0+r)*(NKVh*Dd) + kvh*Dd + dq);
            S.KV[r][dq+0] = __uint_as_float(f2tf(vv.x));
            S.KV[r][dq+1] = __uint_as_float(f2tf(vv.y));
            S.KV[r][dq+2] = __uint_as_float(f2tf(vv.z));
            S.KV[r][dq+3] = __uint_as_float(f2tf(vv.w));
        }
        __syncthreads();
        // O += P V  (warp: 16 rows x 128 d-cols; k = 64 kv)
        #pragma unroll
        for (int kk = 0; kk < 8; kk++) {
            const int kb = kk*8;
            unsigned a0 = __float_as_uint(S.Ps[rA  ][kb+t  ]);
            unsigned a1 = __float_as_uint(S.Ps[rA+8][kb+t  ]);
            unsigned a2 = __float_as_uint(S.Ps[rA  ][kb+t+4]);
            unsigned a3 = __float_as_uint(S.Ps[rA+8][kb+t+4]);
            #pragma unroll
            for (int nt = 0; nt < 16; nt++) {
                unsigned b0 = __float_as_uint(S.KV[kb+t  ][nt*8+g]);
                unsigned b1 = __float_as_uint(S.KV[kb+t+4][nt*8+g]);
                MMA_TF32(o[nt], a0,a1,a2,a3, b0,b1);
            }
        }
    }

    float inv0 = 1.0f / l0, inv1 = 1.0f / l1;
    #pragma unroll
    for (int nt = 0; nt < 16; nt++) {
        int col = nt*8 + t*2;
        float2 v0, v1;
        v0.x = o[nt][0]*inv0; v0.y = o[nt][1]*inv0;
        v1.x = o[nt][2]*inv1; v1.y = o[nt][3]*inv1;
        *(float2*)(O + (size_t)(tq0+rA)*Hh   + h*Dd + col) = v0;
        *(float2*)(O + (size_t)(tq0+rA+8)*Hh + h*Dd + col) = v1;
    }
}

// ---------------- rmsnorm ----------------
__global__ __launch_bounds__(256) void rmsnorm_kernel(
    const float* __restrict__ x, const float* __restrict__ w, float* __restrict__ y)
{
    int t = blockIdx.x;
    const float* xr = x + (size_t)t*Hh;
    float s = 0.f;
    for (int i = threadIdx.x; i < Hh; i += 256) { float v = xr[i]; s += v*v; }
    #pragma unroll
    for (int o = 16; o > 0; o >>= 1) s += __shfl_xor_sync(0xffffffffu, s, o);
    __shared__ float red[8];
    if ((threadIdx.x & 31) == 0) red[threadIdx.x >> 5] = s;
    __syncthreads();
    float tot = 0.f;
    #pragma unroll
    for (int wv = 0; wv < 8; wv++) tot += red[wv];
    float inv = rsqrtf(tot * (1.0f/(float)Hh) + EPSf);
    float* yr = y + (size_t)t*Hh;
    for (int i = threadIdx.x; i < Hh; i += 256) yr[i] = w[i]*xr[i]*inv;
}

// ---------------- RoPE ----------------
__global__ void rope_kernel(float* __restrict__ a, int nheads,
                            const int* __restrict__ pos_ids,
                            const float* __restrict__ cosb,
                            const float* __restrict__ sinb)
{
    int idx = blockIdx.x*256 + threadIdx.x;
    int total = Tt * nheads * 64;
    if (idx >= total) return;
    int dd = idx & 63;
    int hh = (idx >> 6) % nheads;
    int t  = idx / (64*nheads);
    int pos = pos_ids[t] & 4095;
    float c1 = cosb[pos*Dd + dd],      s1 = sinb[pos*Dd + dd];
    float c2 = cosb[pos*Dd + dd + 64], s2 = sinb[pos*Dd + dd + 64];
    float* base = a + (size_t)t*(nheads*Dd) + hh*Dd;
    float x1 = base[dd], x2 = base[dd+64];
    base[dd]     = x1*c1 - x2*s1;
    base[dd+64]  = x2*c2 + x1*s2;
}

// ---------------- router ----------------
__global__ void zero_counts() { if (threadIdx.x < Ee) g_ecount[threadIdx.x] = 0; }

__global__ __launch_bounds__(256) void router_kernel(
    const float* __restrict__ x, const float* __restrict__ rw)
{
    int t = blockIdx.x;
    const float* xr = x + (size_t)t*Hh;
    float acc[Ee];
    #pragma unroll
    for (int e = 0; e < Ee; e++) acc[e] = 0.f;
    for (int hh = threadIdx.x; hh < Hh; hh += 256) {
        float xv = xr[hh];
        #pragma unroll
        for (int e = 0; e < Ee; e++) acc[e] += xv * rw[e*Hh + hh];
    }
    #pragma unroll
    for (int e = 0; e < Ee; e++)
        #pragma unroll
        for (int o = 16; o > 0; o >>= 1) acc[e] += __shfl_xor_sync(0xffffffffu, acc[e], o);
    __shared__ float red[8][Ee];
    int warp = threadIdx.x >> 5, lane = threadIdx.x & 31;
    if (lane == 0)
        for (int e = 0; e < Ee; e++) red[warp][e] = acc[e];
    __syncthreads();
    if (threadIdx.x == 0) {
        float l[Ee];
        for (int e = 0; e < Ee; e++) {
            float ssum = 0.f;
            for (int w = 0; w < 8; w++) ssum += red[w][e];
            l[e] = ssum;
        }
        int i1 = 0;
        for (int e = 1; e < Ee; e++) if (l[e] > l[i1]) i1 = e;
        int i2 = -1;
        for (int e = 0; e < Ee; e++) if (e != i1 && (i2 < 0 || l[e] > l[i2])) i2 = e;
        float w1 = 1.f / (1.f + __expf(l[i2] - l[i1]));
        g_rwflat[2*t]   = w1;
        g_rwflat[2*t+1] = 1.f - w1;
        int p1 = atomicAdd(&g_ecount[i1], 1); g_elist[i1*Tt + p1] = 2*t;
        int p2 = atomicAdd(&g_ecount[i2], 1); g_elist[i2*Tt + p2] = 2*t + 1;
    }
}

// ---------------- elementwise ----------------
__global__ void swiglu_moe_kernel(float* __restrict__ gb, const float* __restrict__ ub)
{
    int idx = blockIdx.x*256 + threadIdx.x;
    int e = idx >> 21;
    int r = (idx >> 9) & 4095;
    if (r >= g_ecount[e]) return;
    float g = gb[idx], u = ub[idx];
    gb[idx] = g * u / (1.f + __expf(-g));
}

__global__ void swiglu_shared_kernel(const float* __restrict__ shg, float* __restrict__ sha)
{
    int idx = blockIdx.x*256 + threadIdx.x;
    int t = idx >> 10;
    int i = idx & 1023;
    float a = shg[(size_t)t*2*ISH + i];
    float b = shg[(size_t)t*2*ISH + ISH + i];
    sha[idx] = a * b / (1.f + __expf(-a));
}

__global__ void combine_kernel(const float* __restrict__ hid,
                               const float* __restrict__ yd,
                               const float* __restrict__ shr,
                               float* __restrict__ out)
{
    int idx = blockIdx.x*256 + threadIdx.x;
    int t = idx / Hh;
    int c = idx - t*Hh;
    float mo = g_rwflat[2*t]   * yd[(size_t)(2*t)*Hh + c]
             + g_rwflat[2*t+1] * yd[(size_t)(2*t+1)*Hh + c];
    out[idx] = hid[idx] + RESMf * (mo + shr[idx]);
}

// ---------------- launch ----------------
extern "C" void kernel_launch(void* const* d_in, const int* in_sizes, int n_in,
                              void* d_out, int out_size)
{
    const float* hidden    = (const float*)d_in[0];
    const int*   pos       = (const int*)  d_in[1];
    const float* cosb      = (const float*)d_in[2];
    const float* sinb      = (const float*)d_in[3];
    const float* ln1       = (const float*)d_in[4];
    const float* ln2       = (const float*)d_in[5];
    const float* wq        = (const float*)d_in[6];
    const float* wk        = (const float*)d_in[7];
    const float* wv        = (const float*)d_in[8];
    const float* wo        = (const float*)d_in[9];
    const float* router_w  = (const float*)d_in[10];
    const float* w_gate    = (const float*)d_in[11];
    const float* w_up      = (const float*)d_in[12];
    const float* w_down    = (const float*)d_in[13];
    const float* shared_in = (const float*)d_in[14];
    const float* shared_ot = (const float*)d_in[15];
    float* out = (float*)d_out;

    float *p_xnorm, *p_q, *p_k, *p_v, *p_attn, *p_hidden, *p_x2;
    float *p_shg, *p_shh, *p_shared, *p_gbuf, *p_ubuf, *p_ydown;
    cudaGetSymbolAddress((void**)&p_xnorm,  g_xnorm);
    cudaGetSymbolAddress((void**)&p_q,      g_q);
    cudaGetSymbolAddress((void**)&p_k,      g_k);
    cudaGetSymbolAddress((void**)&p_v,      g_v);
    cudaGetSymbolAddress((void**)&p_attn,   g_attn);
    cudaGetSymbolAddress((void**)&p_hidden, g_hidden);
    cudaGetSymbolAddress((void**)&p_x2,     g_x2);
    cudaGetSymbolAddress((void**)&p_shg,    g_shgate);
    cudaGetSymbolAddress((void**)&p_shh,    g_shh);
    cudaGetSymbolAddress((void**)&p_shared, g_shared);
    cudaGetSymbolAddress((void**)&p_gbuf,   g_gbuf);
    cudaGetSymbolAddress((void**)&p_ubuf,   g_ubuf);
    cudaGetSymbolAddress((void**)&p_ydown,  g_ydown);

    cudaFuncSetAttribute(tc_gemm,     cudaFuncAttributeMaxDynamicSharedMemorySize, SMEM_BYTES);
    cudaFuncSetAttribute(tc_qkv,      cudaFuncAttributeMaxDynamicSharedMemorySize, SMEM_BYTES);
    cudaFuncSetAttribute(tc_moe_gu,   cudaFuncAttributeMaxDynamicSharedMemorySize, SMEM_BYTES);
    cudaFuncSetAttribute(tc_moe_down, cudaFuncAttributeMaxDynamicSharedMemorySize, SMEM_BYTES);
    cudaFuncSetAttribute(tc_attn,     cudaFuncAttributeMaxDynamicSharedMemorySize, ATTN_SMEM);

    // ---- attention block ----
    rmsnorm_kernel<<<Tt, 256>>>(hidden, ln1, p_xnorm);
    tc_qkv<<<dim3(20,32), 256, SMEM_BYTES>>>(p_xnorm, wq, wk, wv, p_q, p_k, p_v);
    rope_kernel<<<(Tt*NHq*64 + 255)/256, 256>>>(p_q, NHq, pos, cosb, sinb);
    rope_kernel<<<(Tt*NKVh*64 + 255)/256, 256>>>(p_k, NKVh, pos, cosb, sinb);
    tc_attn<<<dim3(Ss/64, NHq, Bb), 128, ATTN_SMEM>>>(p_q, p_k, p_v, p_attn);
    tc_gemm<<<dim3(12,32), 256, SMEM_BYTES>>>(p_attn, Hh, wo, Hh, p_hidden, Hh, Hh, RESMf, hidden);

    // ---- MoE + shared MLP block ----
    rmsnorm_kernel<<<Tt, 256>>>(p_hidden, ln2, p_x2);
    zero_counts<<<1, 32>>>();
    router_kernel<<<Tt, 256>>>(p_x2, router_w);
    tc_gemm<<<dim3(16,32), 256, SMEM_BYTES>>>(p_x2, Hh, shared_in, Hh, p_shg, 2*ISH, Hh, 1.f, nullptr);
    tc_moe_gu<<<dim3(8,32,Ee), 256, SMEM_BYTES>>>(p_x2, w_gate, w_up, p_gbuf, p_ubuf);
    swiglu_moe_kernel<<<(Ee*Tt*IEXP)/256, 256>>>(p_gbuf, p_ubuf);
    tc_moe_down<<<dim3(12,32,Ee), 256, SMEM_BYTES>>>(p_gbuf, w_down, p_ydown);
    swiglu_shared_kernel<<<(Tt*ISH)/256, 256>>>(p_shg, p_shh);
    tc_gemm<<<dim3(12,32), 256, SMEM_BYTES>>>(p_shh, ISH, shared_ot, ISH, p_shared, Hh, ISH, 1.f, nullptr);
    combine_kernel<<<(Tt*Hh)/256, 256>>>(p_hidden, p_ydown, p_shared, out);
}

// round 14
// speedup vs baseline: 4.3846x; 1.2294x over previous
#include <cuda_runtime.h>
#include <cstdint>

// ---------------- problem constants ----------------
#define Bb 2
#define Ss 2048
#define Hh 1536
#define NHq 12
#define NKVh 4
#define Dd 128
#define Tt (Bb*Ss)          // 4096
#define Ee 8
#define IEXP 512
#define ISH 1024
#define SCALEf 0.0078125f
#define RESMf 0.22f
#define EPSf 1e-6f

// ---------------- scratch ----------------
__device__ float g_xnorm [Tt*Hh];
__device__ float g_q     [Tt*Hh];
__device__ float g_k     [Tt*NKVh*Dd];
__device__ float g_v     [Tt*NKVh*Dd];
__device__ float g_attn  [Tt*Hh];
__device__ float g_hidden[Tt*Hh];
__device__ float g_x2    [Tt*Hh];
__device__ float g_shgate[Tt*2*ISH];
__device__ float g_shh   [Tt*ISH];
__device__ float g_shared[Tt*Hh];
__device__ float g_gbuf  [Ee*Tt*IEXP];
__device__ float g_ubuf  [Ee*Tt*IEXP];
__device__ float g_ydown [Tt*2*Hh];
__device__ int   g_elist [Ee*Tt];
__device__ int   g_ecount[Ee];
__device__ float g_rwflat[Tt*2];

// ---------------- bf16 helpers ----------------
// pack two fp32 -> bf16x2 (lo = first arg)
__device__ __forceinline__ unsigned pk(float lo, float hi)
{
    unsigned r;
    asm("cvt.rn.bf16x2.f32 %0, %1, %2;" : "=r"(r) : "f"(hi), "f"(lo));
    return r;
}

#define MMA_BF16(acc, a0,a1,a2,a3, b0,b1) \
    asm volatile( \
        "mma.sync.aligned.m16n8k16.row.col.f32.bf16.bf16.f32 " \
        "{%0,%1,%2,%3}, {%4,%5,%6,%7}, {%8,%9}, {%0,%1,%2,%3};" \
        : "+f"((acc)[0]), "+f"((acc)[1]), "+f"((acc)[2]), "+f"((acc)[3]) \
        : "r"(a0), "r"(a1), "r"(a2), "r"(a3), "r"(b0), "r"(b1))

struct SmemT {
    unsigned short As[2][128][40];
    unsigned short Bs[2][128][40];
};
#define SMEM_BYTES ((int)sizeof(SmemT))   // 40960

// warp tile 32x64; k-chunk 32 = 2 x k16 mma steps
__device__ __forceinline__ void mma_compute(
    const unsigned short (&A)[128][40], const unsigned short (&B)[128][40],
    int lane, int wm, int wn, float (&acc)[2][8][4])
{
    const int g = lane >> 2, t2 = (lane & 3)*2;
    #pragma unroll
    for (int kk = 0; kk < 2; kk++) {
        const int kb = kk*16;
        unsigned af[2][4];
        #pragma unroll
        for (int mt = 0; mt < 2; mt++) {
            int ar = wm*32 + mt*16 + g;
            af[mt][0] = *(const unsigned*)&A[ar  ][kb + t2];
            af[mt][1] = *(const unsigned*)&A[ar+8][kb + t2];
            af[mt][2] = *(const unsigned*)&A[ar  ][kb + t2 + 8];
            af[mt][3] = *(const unsigned*)&A[ar+8][kb + t2 + 8];
        }
        #pragma unroll
        for (int nt = 0; nt < 8; nt++) {
            int br = wn*64 + nt*8 + g;
            unsigned b0 = *(const unsigned*)&B[br][kb + t2];
            unsigned b1 = *(const unsigned*)&B[br][kb + t2 + 8];
            #pragma unroll
            for (int mt = 0; mt < 2; mt++)
                MMA_BF16(acc[mt][nt], af[mt][0],af[mt][1],af[mt][2],af[mt][3], b0,b1);
        }
    }
}

// double-buffered K loop; row = tid>>1, c0off = (tid&1)*16 (elements)
__device__ __forceinline__ void bf16_db(
    SmemT& S, const float* ag, const float* bg,
    int row, int c0off, int K,
    int lane, int wm, int wn, float (&acc)[2][8][4])
{
    #pragma unroll
    for (int i = 0; i < 4; i++) {
        float4 a = ag ? *(const float4*)(ag + i*4) : make_float4(0.f,0.f,0.f,0.f);
        float4 b = *(const float4*)(bg + i*4);
        *(unsigned*)&S.As[0][row][c0off + i*4    ] = pk(a.x, a.y);
        *(unsigned*)&S.As[0][row][c0off + i*4 + 2] = pk(a.z, a.w);
        *(unsigned*)&S.Bs[0][row][c0off + i*4    ] = pk(b.x, b.y);
        *(unsigned*)&S.Bs[0][row][c0off + i*4 + 2] = pk(b.z, b.w);
    }
    __syncthreads();

    int cur = 0;
    for (int k0 = 32; k0 < K; k0 += 32) {
        float4 an[4], bn[4];
        #pragma unroll
        for (int i = 0; i < 4; i++) {
            an[i] = ag ? *(const float4*)(ag + k0 + i*4) : make_float4(0.f,0.f,0.f,0.f);
            bn[i] = *(const float4*)(bg + k0 + i*4);
        }
        mma_compute(S.As[cur], S.Bs[cur], lane, wm, wn, acc);
        int nxt = cur ^ 1;
        #pragma unroll
        for (int i = 0; i < 4; i++) {
            *(unsigned*)&S.As[nxt][row][c0off + i*4    ] = pk(an[i].x, an[i].y);
            *(unsigned*)&S.As[nxt][row][c0off + i*4 + 2] = pk(an[i].z, an[i].w);
            *(unsigned*)&S.Bs[nxt][row][c0off + i*4    ] = pk(bn[i].x, bn[i].y);
            *(unsigned*)&S.Bs[nxt][row][c0off + i*4 + 2] = pk(bn[i].z, bn[i].w);
        }
        __syncthreads();
        cur = nxt;
    }
    mma_compute(S.As[cur], S.Bs[cur], lane, wm, wn, acc);
}

// ---------------- generic TN GEMM (bf16) ----------------
__global__ void __launch_bounds__(256, 2) tc_gemm(
    const float* __restrict__ A, int lda,
    const float* __restrict__ B, int ldb,
    float* __restrict__ C, int ldc,
    int K, float alpha, const float* __restrict__ res)
{
    extern __shared__ char smemraw[];
    SmemT& S = *reinterpret_cast<SmemT*>(smemraw);
    const int tid = threadIdx.x, lane = tid & 31, warp = tid >> 5;
    const int wm = warp & 3, wn = warp >> 2;
    const int m0 = blockIdx.y*128, n0 = blockIdx.x*128;
    const int row = tid >> 1, c0off = (tid & 1)*16;
    const float* ag = A + (size_t)(m0+row)*lda + c0off;
    const float* bg = B + (size_t)(n0+row)*ldb + c0off;

    float acc[2][8][4];
    #pragma unroll
    for (int i=0;i<2;i++) for (int j=0;j<8;j++) for (int c=0;c<4;c++) acc[i][j][c]=0.f;

    bf16_db(S, ag, bg, row, c0off, K, lane, wm, wn, acc);

    const int g = lane >> 2, t = lane & 3;
    #pragma unroll
    for (int mt = 0; mt < 2; mt++) {
        int gm = m0 + wm*32 + mt*16 + g;
        #pragma unroll
        for (int nt = 0; nt < 8; nt++) {
            int gn = n0 + wn*64 + nt*8 + t*2;
            float2 v0, v1;
            v0.x = alpha*acc[mt][nt][0]; v0.y = alpha*acc[mt][nt][1];
            v1.x = alpha*acc[mt][nt][2]; v1.y = alpha*acc[mt][nt][3];
            if (res) {
                const float* r0 = res + (size_t)gm*ldc + gn;
                const float* r1 = res + (size_t)(gm+8)*ldc + gn;
                v0.x += r0[0]; v0.y += r0[1];
                v1.x += r1[0]; v1.y += r1[1];
            }
            *(float2*)(C + (size_t)gm*ldc + gn)     = v0;
            *(float2*)(C + (size_t)(gm+8)*ldc + gn) = v1;
        }
    }
}

// ---------------- fused QKV (bf16) ----------------
__global__ void __launch_bounds__(256, 2) tc_qkv(
    const float* __restrict__ A,
    const float* __restrict__ wq, const float* __restrict__ wk, const float* __restrict__ wv,
    float* __restrict__ q, float* __restrict__ k, float* __restrict__ v)
{
    extern __shared__ char smemraw[];
    SmemT& S = *reinterpret_cast<SmemT*>(smemraw);
    const int bx = blockIdx.x;
    const float* B; float* C; int ldc, n0;
    if (bx < 12)      { B = wq; C = q; ldc = Hh;      n0 = bx*128; }
    else if (bx < 16) { B = wk; C = k; ldc = NKVh*Dd; n0 = (bx-12)*128; }
    else              { B = wv; C = v; ldc = NKVh*Dd; n0 = (bx-16)*128; }

    const int tid = threadIdx.x, lane = tid & 31, warp = tid >> 5;
    const int wm = warp & 3, wn = warp >> 2;
    const int m0 = blockIdx.y*128;
    const int row = tid >> 1, c0off = (tid & 1)*16;
    const float* ag = A + (size_t)(m0+row)*Hh + c0off;
    const float* bg = B + (size_t)(n0+row)*Hh + c0off;

    float acc[2][8][4];
    #pragma unroll
    for (int i=0;i<2;i++) for (int j=0;j<8;j++) for (int c=0;c<4;c++) acc[i][j][c]=0.f;

    bf16_db(S, ag, bg, row, c0off, Hh, lane, wm, wn, acc);

    const int g = lane >> 2, t = lane & 3;
    #pragma unroll
    for (int mt = 0; mt < 2; mt++) {
        int gm = m0 + wm*32 + mt*16 + g;
        #pragma unroll
        for (int nt = 0; nt < 8; nt++) {
            int gn = n0 + wn*64 + nt*8 + t*2;
            float2 v0, v1;
            v0.x = acc[mt][nt][0]; v0.y = acc[mt][nt][1];
            v1.x = acc[mt][nt][2]; v1.y = acc[mt][nt][3];
            *(float2*)(C + (size_t)gm*ldc + gn)     = v0;
            *(float2*)(C + (size_t)(gm+8)*ldc + gn) = v1;
        }
    }
}

// ---------------- MoE gate+up (bf16, gathered rows) ----------------
__global__ void __launch_bounds__(256, 2) tc_moe_gu(
    const float* __restrict__ X,
    const float* __restrict__ w_gate, const float* __restrict__ w_up,
    float* __restrict__ gbuf, float* __restrict__ ubuf)
{
    const int e = blockIdx.z;
    const int count = g_ecount[e];
    const int m0 = blockIdx.y*128;
    if (m0 >= count) return;
    extern __shared__ char smemraw[];
    SmemT& S = *reinterpret_cast<SmemT*>(smemraw);
    __shared__ int rowmap[128];

    const int bx = blockIdx.x;
    const float* B = (bx < 4 ? w_gate : w_up) + (size_t)e*IEXP*Hh;
    float* C = (bx < 4 ? gbuf : ubuf);
    const int n0 = (bx & 3)*128;

    const int tid = threadIdx.x, lane = tid & 31, warp = tid >> 5;
    const int wm = warp & 3, wn = warp >> 2;
    const int row = tid >> 1, c0off = (tid & 1)*16;
    if (tid < 128) {
        int r = m0 + tid;
        rowmap[tid] = (r < count) ? (g_elist[e*Tt + r] >> 1) : -1;
    }
    __syncthreads();
    int src = rowmap[row];
    const float* ag = (src >= 0) ? X + (size_t)src*Hh + c0off : nullptr;
    const float* bg = B + (size_t)(n0+row)*Hh + c0off;

    float acc[2][8][4];
    #pragma unroll
    for (int i=0;i<2;i++) for (int j=0;j<8;j++) for (int c=0;c<4;c++) acc[i][j][c]=0.f;

    bf16_db(S, ag, bg, row, c0off, Hh, lane, wm, wn, acc);

    const int g = lane >> 2, t = lane & 3;
    #pragma unroll
    for (int mt = 0; mt < 2; mt++) {
        int r0 = m0 + wm*32 + mt*16 + g;
        #pragma unroll
        for (int nt = 0; nt < 8; nt++) {
            int gn = n0 + wn*64 + nt*8 + t*2;
            if (r0 < count) {
                float2 v; v.x = acc[mt][nt][0]; v.y = acc[mt][nt][1];
                *(float2*)(C + ((size_t)e*Tt + r0)*IEXP + gn) = v;
            }
            if (r0+8 < count) {
                float2 v; v.x = acc[mt][nt][2]; v.y = acc[mt][nt][3];
                *(float2*)(C + ((size_t)e*Tt + r0+8)*IEXP + gn) = v;
            }
        }
    }
}

// ---------------- MoE down (bf16, scatter rows) ----------------
__global__ void __launch_bounds__(256, 2) tc_moe_down(
    const float* __restrict__ Gact,
    const float* __restrict__ w_down,
    float* __restrict__ ydown)
{
    const int e = blockIdx.z;
    const int count = g_ecount[e];
    const int m0 = blockIdx.y*128;
    if (m0 >= count) return;
    extern __shared__ char smemraw[];
    SmemT& S = *reinterpret_cast<SmemT*>(smemraw);

    const float* B = w_down + (size_t)e*Hh*IEXP;
    const int n0 = blockIdx.x*128;
    const int tid = threadIdx.x, lane = tid & 31, warp = tid >> 5;
    const int wm = warp & 3, wn = warp >> 2;
    const int row = tid >> 1, c0off = (tid & 1)*16;
    const float* ag = Gact + ((size_t)e*Tt + m0 + row)*IEXP + c0off;
    const float* bg = B + (size_t)(n0+row)*IEXP + c0off;

    float acc[2][8][4];
    #pragma unroll
    for (int i=0;i<2;i++) for (int j=0;j<8;j++) for (int c=0;c<4;c++) acc[i][j][c]=0.f;

    bf16_db(S, ag, bg, row, c0off, IEXP, lane, wm, wn, acc);

    const int* lst = g_elist + e*Tt;
    const int g = lane >> 2, t = lane & 3;
    #pragma unroll
    for (int mt = 0; mt < 2; mt++) {
        int r0 = m0 + wm*32 + mt*16 + g;
        #pragma unroll
        for (int nt = 0; nt < 8; nt++) {
            int gn = n0 + wn*64 + nt*8 + t*2;
            if (r0 < count) {
                float2 v; v.x = acc[mt][nt][0]; v.y = acc[mt][nt][1];
                *(float2*)(ydown + (size_t)lst[r0]*Hh + gn) = v;
            }
            if (r0+8 < count) {
                float2 v; v.x = acc[mt][nt][2]; v.y = acc[mt][nt][3];
                *(float2*)(ydown + (size_t)lst[r0+8]*Hh + gn) = v;
            }
        }
    }
}

// ---------------- bf16 flash attention: 64q x 64kv tiles, 4 warps ----------------
struct AttnSmem {
    unsigned short Qs[64][136];   // 17408 B
    char kvbuf[18432];            // K tile ushort[64][136] OR VP unsigned[128][36]
    unsigned short Ps[64][72];    // 9216 B
};
#define ATTN_SMEM ((int)sizeof(AttnSmem))  // 45056

__global__ void __launch_bounds__(128, 2) tc_attn(
    const float* __restrict__ Q, const float* __restrict__ Kg,
    const float* __restrict__ Vg, float* __restrict__ O)
{
    extern __shared__ char sraw[];
    AttnSmem& S = *reinterpret_cast<AttnSmem*>(sraw);
    unsigned short (*Ks)[136] = reinterpret_cast<unsigned short (*)[136]>(S.kvbuf);
    unsigned (*VP)[36]        = reinterpret_cast<unsigned (*)[36]>(S.kvbuf);

    const int qt = blockIdx.x, h = blockIdx.y, b = blockIdx.z;
    const int kvh = h / (NHq/NKVh);
    const int tid = threadIdx.x, lane = tid & 31, warp = tid >> 5;
    const int g = lane >> 2, t = lane & 3, t2 = t*2;
    const int tq0 = b*Ss + qt*64;
    const int rA = warp*16 + g;

    // load Q tile (scaled, bf16)
    #pragma unroll
    for (int i = 0; i < 16; i++) {
        int v = tid + i*128;
        int r = v >> 5, dq = (v & 31) << 2;
        float4 qv = *(const float4*)(Q + (size_t)(tq0+r)*Hh + h*Dd + dq);
        *(unsigned*)&S.Qs[r][dq]   = pk(qv.x*SCALEf, qv.y*SCALEf);
        *(unsigned*)&S.Qs[r][dq+2] = pk(qv.z*SCALEf, qv.w*SCALEf);
    }

    float o[16][4];
    #pragma unroll
    for (int i = 0; i < 16; i++)
        #pragma unroll
        for (int c = 0; c < 4; c++) o[i][c] = 0.f;
    float m0v = -1e30f, m1v = -1e30f, l0 = 0.f, l1 = 0.f;

    for (int kt = 0; kt <= qt; kt++) {
        const int tk0 = b*Ss + kt*64;
        __syncthreads();
        #pragma unroll
        for (int i = 0; i < 16; i++) {
            int v = tid + i*128;
            int r = v >> 5, dq = (v & 31) << 2;
            float4 kv = *(const float4*)(Kg + (size_t)(tk0+r)*(NKVh*Dd) + kvh*Dd + dq);
            *(unsigned*)&Ks[r][dq]   = pk(kv.x, kv.y);
            *(unsigned*)&Ks[r][dq+2] = pk(kv.z, kv.w);
        }
        __syncthreads();

        // S = Q K^T  (warp: 16 rows x 64 cols), Dd=128 -> 8 k16 steps
        float s[8][4];
        #pragma unroll
        for (int nt = 0; nt < 8; nt++)
            #pragma unroll
            for (int c = 0; c < 4; c++) s[nt][c] = 0.f;
        #pragma unroll
        for (int kk = 0; kk < 8; kk++) {
            const int kb = kk*16;
            unsigned a0 = *(const unsigned*)&S.Qs[rA  ][kb + t2];
            unsigned a1 = *(const unsigned*)&S.Qs[rA+8][kb + t2];
            unsigned a2 = *(const unsigned*)&S.Qs[rA  ][kb + t2 + 8];
            unsigned a3 = *(const unsigned*)&S.Qs[rA+8][kb + t2 + 8];
            #pragma unroll
            for (int nt = 0; nt < 8; nt++) {
                unsigned b0 = *(const unsigned*)&Ks[nt*8+g][kb + t2];
                unsigned b1 = *(const unsigned*)&Ks[nt*8+g][kb + t2 + 8];
                MMA_BF16(s[nt], a0,a1,a2,a3, b0,b1);
            }
        }
        if (kt == qt) {
            #pragma unroll
            for (int nt = 0; nt < 8; nt++)
                #pragma unroll
                for (int j = 0; j < 2; j++) {
                    int col = nt*8 + t2 + j;
                    if (col > rA)   s[nt][j]   = -1e30f;
                    if (col > rA+8) s[nt][2+j] = -1e30f;
                }
        }
        // online softmax
        float mx0 = -1e30f, mx1 = -1e30f;
        #pragma unroll
        for (int nt = 0; nt < 8; nt++) {
            mx0 = fmaxf(mx0, fmaxf(s[nt][0], s[nt][1]));
            mx1 = fmaxf(mx1, fmaxf(s[nt][2], s[nt][3]));
        }
        mx0 = fmaxf(mx0, __shfl_xor_sync(0xffffffffu, mx0, 1));
        mx0 = fmaxf(mx0, __shfl_xor_sync(0xffffffffu, mx0, 2));
        mx1 = fmaxf(mx1, __shfl_xor_sync(0xffffffffu, mx1, 1));
        mx1 = fmaxf(mx1, __shfl_xor_sync(0xffffffffu, mx1, 2));
        float mn0 = fmaxf(m0v, mx0), mn1 = fmaxf(m1v, mx1);
        float sc0 = __expf(m0v - mn0), sc1 = __expf(m1v - mn1);
        float sum0 = 0.f, sum1 = 0.f;
        #pragma unroll
        for (int nt = 0; nt < 8; nt++) {
            float p0 = __expf(s[nt][0] - mn0);
            float p1 = __expf(s[nt][1] - mn0);
            float p2 = __expf(s[nt][2] - mn1);
            float p3 = __expf(s[nt][3] - mn1);
            sum0 += p0 + p1; sum1 += p2 + p3;
            int c = nt*8 + t2;
            *(unsigned*)&S.Ps[rA  ][c] = pk(p0, p1);
            *(unsigned*)&S.Ps[rA+8][c] = pk(p2, p3);
        }
        sum0 += __shfl_xor_sync(0xffffffffu, sum0, 1);
        sum0 += __shfl_xor_sync(0xffffffffu, sum0, 2);
        sum1 += __shfl_xor_sync(0xffffffffu, sum1, 1);
        sum1 += __shfl_xor_sync(0xffffffffu, sum1, 2);
        l0 = l0*sc0 + sum0; l1 = l1*sc1 + sum1;
        m0v = mn0; m1v = mn1;
        #pragma unroll
        for (int nt = 0; nt < 16; nt++) {
            o[nt][0] *= sc0; o[nt][1] *= sc0;
            o[nt][2] *= sc1; o[nt][3] *= sc1;
        }
        __syncthreads();   // Ps written; K reads done -> reuse kvbuf for VP
        // load V tile as kv-pairs: VP[d][p] = {V[2p][d], V[2p+1][d]}
        #pragma unroll
        for (int i = 0; i < 16; i++) {
            int idx = tid + i*128;           // 0..2047
            int p   = idx >> 6;              // kv pair 0..31
            int d2  = (idx & 63) << 1;       // d 0,2,..,126
            const float* vb = Vg + (size_t)(tk0 + 2*p)*(NKVh*Dd) + kvh*Dd + d2;
            float2 r0 = *(const float2*)(vb);
            float2 r1 = *(const float2*)(vb + NKVh*Dd);
            VP[d2  ][p] = pk(r0.x, r1.x);
            VP[d2+1][p] = pk(r0.y, r1.y);
        }
        __syncthreads();
        // O += P V : kv=64 -> 4 k16 steps; d cols = 16 n8 tiles
        #pragma unroll
        for (int kk = 0; kk < 4; kk++) {
            const int kb = kk*16;            // halves
            const int kw = kk*8;             // VP word offset
            unsigned a0 = *(const unsigned*)&S.Ps[rA  ][kb + t2];
            unsigned a1 = *(const unsigned*)&S.Ps[rA+8][kb + t2];
            unsigned a2 = *(const unsigned*)&S.Ps[rA  ][kb + t2 + 8];
            unsigned a3 = *(const unsigned*)&S.Ps[rA+8][kb + t2 + 8];
            #pragma unroll
            for (int nt = 0; nt < 16; nt++) {
                unsigned b0 = VP[nt*8+g][kw + t];
                unsigned b1 = VP[nt*8+g][kw + t + 4];
                MMA_BF16(o[nt], a0,a1,a2,a3, b0,b1);
            }
        }
    }

    float inv0 = 1.0f / l0, inv1 = 1.0f / l1;
    #pragma unroll
    for (int nt = 0; nt < 16; nt++) {
        int col = nt*8 + t2;
        float2 v0, v1;
        v0.x = o[nt][0]*inv0; v0.y = o[nt][1]*inv0;
        v1.x = o[nt][2]*inv1; v1.y = o[nt][3]*inv1;
        *(float2*)(O + (size_t)(tq0+rA)*Hh   + h*Dd + col) = v0;
        *(float2*)(O + (size_t)(tq0+rA+8)*Hh + h*Dd + col) = v1;
    }
}

// ---------------- rmsnorm ----------------
__global__ __launch_bounds__(256) void rmsnorm_kernel(
    const float* __restrict__ x, const float* __restrict__ w, float* __restrict__ y)
{
    int t = blockIdx.x;
    const float* xr = x + (size_t)t*Hh;
    float s = 0.f;
    for (int i = threadIdx.x; i < Hh; i += 256) { float v = xr[i]; s += v*v; }
    #pragma unroll
    for (int o = 16; o > 0; o >>= 1) s += __shfl_xor_sync(0xffffffffu, s, o);
    __shared__ float red[8];
    if ((threadIdx.x & 31) == 0) red[threadIdx.x >> 5] = s;
    __syncthreads();
    float tot = 0.f;
    #pragma unroll
    for (int wv = 0; wv < 8; wv++) tot += red[wv];
    float inv = rsqrtf(tot * (1.0f/(float)Hh) + EPSf);
    float* yr = y + (size_t)t*Hh;
    for (int i = threadIdx.x; i < Hh; i += 256) yr[i] = w[i]*xr[i]*inv;
}

// ---------------- RoPE ----------------
__global__ void rope_kernel(float* __restrict__ a, int nheads,
                            const int* __restrict__ pos_ids,
                            const float* __restrict__ cosb,
                            const float* __restrict__ sinb)
{
    int idx = blockIdx.x*256 + threadIdx.x;
    int total = Tt * nheads * 64;
    if (idx >= total) return;
    int dd = idx & 63;
    int hh = (idx >> 6) % nheads;
    int t  = idx / (64*nheads);
    int pos = pos_ids[t] & 4095;
    float c1 = cosb[pos*Dd + dd],      s1 = sinb[pos*Dd + dd];
    float c2 = cosb[pos*Dd + dd + 64], s2 = sinb[pos*Dd + dd + 64];
    float* base = a + (size_t)t*(nheads*Dd) + hh*Dd;
    float x1 = base[dd], x2 = base[dd+64];
    base[dd]     = x1*c1 - x2*s1;
    base[dd+64]  = x2*c2 + x1*s2;
}

// ---------------- router ----------------
__global__ void zero_counts() { if (threadIdx.x < Ee) g_ecount[threadIdx.x] = 0; }

__global__ __launch_bounds__(256) void router_kernel(
    const float* __restrict__ x, const float* __restrict__ rw)
{
    int t = blockIdx.x;
    const float* xr = x + (size_t)t*Hh;
    float acc[Ee];
    #pragma unroll
    for (int e = 0; e < Ee; e++) acc[e] = 0.f;
    for (int hh = threadIdx.x; hh < Hh; hh += 256) {
        float xv = xr[hh];
        #pragma unroll
        for (int e = 0; e < Ee; e++) acc[e] += xv * rw[e*Hh + hh];
    }
    #pragma unroll
    for (int e = 0; e < Ee; e++)
        #pragma unroll
        for (int o = 16; o > 0; o >>= 1) acc[e] += __shfl_xor_sync(0xffffffffu, acc[e], o);
    __shared__ float red[8][Ee];
    int warp = threadIdx.x >> 5, lane = threadIdx.x & 31;
    if (lane == 0)
        for (int e = 0; e < Ee; e++) red[warp][e] = acc[e];
    __syncthreads();
    if (threadIdx.x == 0) {
        float l[Ee];
        for (int e = 0; e < Ee; e++) {
            float ssum = 0.f;
            for (int w = 0; w < 8; w++) ssum += red[w][e];
            l[e] = ssum;
        }
        int i1 = 0;
        for (int e = 1; e < Ee; e++) if (l[e] > l[i1]) i1 = e;
        int i2 = -1;
        for (int e = 0; e < Ee; e++) if (e != i1 && (i2 < 0 || l[e] > l[i2])) i2 = e;
        float w1 = 1.f / (1.f + __expf(l[i2] - l[i1]));
        g_rwflat[2*t]   = w1;
        g_rwflat[2*t+1] = 1.f - w1;
        int p1 = atomicAdd(&g_ecount[i1], 1); g_elist[i1*Tt + p1] = 2*t;
        int p2 = atomicAdd(&g_ecount[i2], 1); g_elist[i2*Tt + p2] = 2*t + 1;
    }
}

// ---------------- elementwise ----------------
__global__ void swiglu_moe_kernel(float* __restrict__ gb, const float* __restrict__ ub)
{
    int idx = blockIdx.x*256 + threadIdx.x;
    int e = idx >> 21;
    int r = (idx >> 9) & 4095;
    if (r >= g_ecount[e]) return;
    float g = gb[idx], u = ub[idx];
    gb[idx] = g * u / (1.f + __expf(-g));
}

__global__ void swiglu_shared_kernel(const float* __restrict__ shg, float* __restrict__ sha)
{
    int idx = blockIdx.x*256 + threadIdx.x;
    int t = idx >> 10;
    int i = idx & 1023;
    float a = shg[(size_t)t*2*ISH + i];
    float b = shg[(size_t)t*2*ISH + ISH + i];
    sha[idx] = a * b / (1.f + __expf(-a));
}

__global__ void combine_kernel(const float* __restrict__ hid,
                               const float* __restrict__ yd,
                               const float* __restrict__ shr,
                               float* __restrict__ out)
{
    int idx = blockIdx.x*256 + threadIdx.x;
    int t = idx / Hh;
    int c = idx - t*Hh;
    float mo = g_rwflat[2*t]   * yd[(size_t)(2*t)*Hh + c]
             + g_rwflat[2*t+1] * yd[(size_t)(2*t+1)*Hh + c];
    out[idx] = hid[idx] + RESMf * (mo + shr[idx]);
}

// ---------------- launch ----------------
extern "C" void kernel_launch(void* const* d_in, const int* in_sizes, int n_in,
                              void* d_out, int out_size)
{
    const float* hidden    = (const float*)d_in[0];
    const int*   pos       = (const int*)  d_in[1];
    const float* cosb      = (const float*)d_in[2];
    const float* sinb      = (const float*)d_in[3];
    const float* ln1       = (const float*)d_in[4];
    const float* ln2       = (const float*)d_in[5];
    const float* wq        = (const float*)d_in[6];
    const float* wk        = (const float*)d_in[7];
    const float* wv        = (const float*)d_in[8];
    const float* wo        = (const float*)d_in[9];
    const float* router_w  = (const float*)d_in[10];
    const float* w_gate    = (const float*)d_in[11];
    const float* w_up      = (const float*)d_in[12];
    const float* w_down    = (const float*)d_in[13];
    const float* shared_in = (const float*)d_in[14];
    const float* shared_ot = (const float*)d_in[15];
    float* out = (float*)d_out;

    float *p_xnorm, *p_q, *p_k, *p_v, *p_attn, *p_hidden, *p_x2;
    float *p_shg, *p_shh, *p_shared, *p_gbuf, *p_ubuf, *p_ydown;
    cudaGetSymbolAddress((void**)&p_xnorm,  g_xnorm);
    cudaGetSymbolAddress((void**)&p_q,      g_q);
    cudaGetSymbolAddress((void**)&p_k,      g_k);
    cudaGetSymbolAddress((void**)&p_v,      g_v);
    cudaGetSymbolAddress((void**)&p_attn,   g_attn);
    cudaGetSymbolAddress((void**)&p_hidden, g_hidden);
    cudaGetSymbolAddress((void**)&p_x2,     g_x2);
    cudaGetSymbolAddress((void**)&p_shg,    g_shgate);
    cudaGetSymbolAddress((void**)&p_shh,    g_shh);
    cudaGetSymbolAddress((void**)&p_shared, g_shared);
    cudaGetSymbolAddress((void**)&p_gbuf,   g_gbuf);
    cudaGetSymbolAddress((void**)&p_ubuf,   g_ubuf);
    cudaGetSymbolAddress((void**)&p_ydown,  g_ydown);

    cudaFuncSetAttribute(tc_gemm,     cudaFuncAttributeMaxDynamicSharedMemorySize, SMEM_BYTES);
    cudaFuncSetAttribute(tc_qkv,      cudaFuncAttributeMaxDynamicSharedMemorySize, SMEM_BYTES);
    cudaFuncSetAttribute(tc_moe_gu,   cudaFuncAttributeMaxDynamicSharedMemorySize, SMEM_BYTES);
    cudaFuncSetAttribute(tc_moe_down, cudaFuncAttributeMaxDynamicSharedMemorySize, SMEM_BYTES);
    cudaFuncSetAttribute(tc_attn,     cudaFuncAttributeMaxDynamicSharedMemorySize, ATTN_SMEM);

    // ---- attention block ----
    rmsnorm_kernel<<<Tt, 256>>>(hidden, ln1, p_xnorm);
    tc_qkv<<<dim3(20,32), 256, SMEM_BYTES>>>(p_xnorm, wq, wk, wv, p_q, p_k, p_v);
    rope_kernel<<<(Tt*NHq*64 + 255)/256, 256>>>(p_q, NHq, pos, cosb, sinb);
    rope_kernel<<<(Tt*NKVh*64 + 255)/256, 256>>>(p_k, NKVh, pos, cosb, sinb);
    tc_attn<<<dim3(Ss/64, NHq, Bb), 128, ATTN_SMEM>>>(p_q, p_k, p_v, p_attn);
    tc_gemm<<<dim3(12,32), 256, SMEM_BYTES>>>(p_attn, Hh, wo, Hh, p_hidden, Hh, Hh, RESMf, hidden);

    // ---- MoE + shared MLP block ----
    rmsnorm_kernel<<<Tt, 256>>>(p_hidden, ln2, p_x2);
    zero_counts<<<1, 32>>>();
    router_kernel<<<Tt, 256>>>(p_x2, router_w);
    tc_gemm<<<dim3(16,32), 256, SMEM_BYTES>>>(p_x2, Hh, shared_in, Hh, p_shg, 2*ISH, Hh, 1.f, nullptr);
    tc_moe_gu<<<dim3(8,32,Ee), 256, SMEM_BYTES>>>(p_x2, w_gate, w_up, p_gbuf, p_ubuf);
    swiglu_moe_kernel<<<(Ee*Tt*IEXP)/256, 256>>>(p_gbuf, p_ubuf);
    tc_moe_down<<<dim3(12,32,Ee), 256, SMEM_BYTES>>>(p_gbuf, w_down, p_ydown);
    swiglu_shared_kernel<<<(Tt*ISH)/256, 256>>>(p_shg, p_shh);
    tc_gemm<<<dim3(12,32), 256, SMEM_BYTES>>>(p_shh, ISH, shared_ot, ISH, p_shared, Hh, ISH, 1.f, nullptr);
    combine_kernel<<<(Tt*Hh)/256, 256>>>(p_hidden, p_ydown, p_shared, out);
}